// round 1
// baseline (speedup 1.0000x reference)
#include <cuda_runtime.h>
#include <math.h>

#define NN 30000
#define EE 480000
#define GG 64
#define HFD 64
#define NHEADS 8
#define MLPD 256

// ---------------- scratch (static device memory; no allocations) ----------------
__device__ float g_h[NN * HFD];                 // projected features
__device__ float g_feat1[NN * NHEADS * HFD];    // 61.4 MB
__device__ float g_res1[NN * NHEADS * HFD];     // 61.4 MB
__device__ float g_el1[NN * NHEADS];
__device__ float g_er1[NN * NHEADS];
__device__ float g_e1[EE * NHEADS];             // 15.4 MB pre-softmax scores
__device__ int   g_cnt[NN];
__device__ int   g_indptr[NN + 1];
__device__ int   g_csr_src[EE];
__device__ int   g_csr_eid[EE];
__device__ float g_h2[NN * HFD];
__device__ float g_feat2[NN * HFD];
__device__ float g_el2[NN];
__device__ float g_er2[NN];
__device__ float g_e2[EE];
__device__ float g_h3[NN * HFD];
__device__ float g_p0[GG * HFD];
__device__ float g_p1[GG * HFD];
__device__ float g_p2[GG * HFD];
__device__ float g_hg[GG * HFD];
__device__ float g_t0[GG * MLPD];
__device__ float g_t1[GG * MLPD];

// ---------------- init ----------------
__global__ void zero_kernel() {
    int i = blockIdx.x * blockDim.x + threadIdx.x;
    if (i < NN) g_cnt[i] = 0;
    if (i < GG * HFD) { g_p0[i] = 0.f; g_p1[i] = 0.f; g_p2[i] = 0.f; }
}

// ---------------- GEMM: Out[nrows,ncols] = A[nrows,64] @ W[64,ncols] (+bias) ----------------
__global__ void gemm_k64(const float* __restrict__ A, const float* __restrict__ W,
                         const float* __restrict__ bias, float* __restrict__ Out,
                         int nrows, int ncols) {
    __shared__ float sA[64 * 64];
    __shared__ float sW[64 * 64];
    int r0 = blockIdx.x * 64;
    int c0 = blockIdx.y * 64;
    int tid = threadIdx.x;  // 256
#pragma unroll
    for (int i = 0; i < 4; i++) {
        int idx = tid + i * 256;         // 1024 float4 slots
        int r = idx >> 4;
        int k4 = (idx & 15) << 2;
        float4 v = make_float4(0.f, 0.f, 0.f, 0.f);
        if (r0 + r < nrows) v = *(const float4*)(A + (size_t)(r0 + r) * 64 + k4);
        *(float4*)(sA + r * 64 + k4) = v;
        int kw = idx >> 4;
        int cw = (idx & 15) << 2;
        *(float4*)(sW + kw * 64 + cw) = *(const float4*)(W + (size_t)kw * ncols + c0 + cw);
    }
    __syncthreads();
    int rt = (tid >> 4) << 2;
    int ct = (tid & 15) << 2;
    float acc[4][4];
#pragma unroll
    for (int i = 0; i < 4; i++)
#pragma unroll
        for (int j = 0; j < 4; j++) acc[i][j] = 0.f;
#pragma unroll 16
    for (int k = 0; k < 64; k++) {
        float a0 = sA[(rt + 0) * 64 + k];
        float a1 = sA[(rt + 1) * 64 + k];
        float a2 = sA[(rt + 2) * 64 + k];
        float a3 = sA[(rt + 3) * 64 + k];
        float4 w = *(const float4*)(sW + k * 64 + ct);
        acc[0][0] += a0 * w.x; acc[0][1] += a0 * w.y; acc[0][2] += a0 * w.z; acc[0][3] += a0 * w.w;
        acc[1][0] += a1 * w.x; acc[1][1] += a1 * w.y; acc[1][2] += a1 * w.z; acc[1][3] += a1 * w.w;
        acc[2][0] += a2 * w.x; acc[2][1] += a2 * w.y; acc[2][2] += a2 * w.z; acc[2][3] += a2 * w.w;
        acc[3][0] += a3 * w.x; acc[3][1] += a3 * w.y; acc[3][2] += a3 * w.z; acc[3][3] += a3 * w.w;
    }
    float4 bv = make_float4(0.f, 0.f, 0.f, 0.f);
    if (bias) bv = *(const float4*)(bias + c0 + ct);
#pragma unroll
    for (int i = 0; i < 4; i++) {
        int r = r0 + rt + i;
        if (r < nrows)
            *(float4*)(Out + (size_t)r * ncols + c0 + ct) =
                make_float4(acc[i][0] + bv.x, acc[i][1] + bv.y, acc[i][2] + bv.z, acc[i][3] + bv.w);
    }
}

// ---------------- segment-sum pool by (sorted) graph_id ----------------
__global__ void pool_kernel(const float* __restrict__ x, float* __restrict__ out,
                            const int* __restrict__ gid) {
    int n0 = blockIdx.x * 256;
    int n1 = min(n0 + 256, NN);
    if (n0 >= NN) return;
    int c = threadIdx.x;  // 64
    int cur = gid[n0];
    float s = 0.f;
    for (int n = n0; n < n1; n++) {
        int g = gid[n];
        if (g != cur) { atomicAdd(&out[cur * HFD + c], s); s = 0.f; cur = g; }
        s += x[(size_t)n * HFD + c];
    }
    atomicAdd(&out[cur * HFD + c], s);
}

// ---------------- layer-1 attention dot products ----------------
__global__ void attn1_kernel(const float* __restrict__ al, const float* __restrict__ ar) {
    int n = blockIdx.x;
    int h = threadIdx.x >> 5, lane = threadIdx.x & 31;
    const float* f = g_feat1 + (size_t)n * 512 + h * 64;
    float a0 = f[lane] * al[h * 64 + lane] + f[lane + 32] * al[h * 64 + lane + 32];
    float b0 = f[lane] * ar[h * 64 + lane] + f[lane + 32] * ar[h * 64 + lane + 32];
#pragma unroll
    for (int o = 16; o; o >>= 1) {
        a0 += __shfl_xor_sync(0xffffffffu, a0, o);
        b0 += __shfl_xor_sync(0xffffffffu, b0, o);
    }
    if (lane == 0) { g_el1[n * 8 + h] = a0; g_er1[n * 8 + h] = b0; }
}

__device__ __forceinline__ float leaky02(float v) { return v > 0.f ? v : 0.2f * v; }

// ---------------- per-edge scores layer 1 (+ in-degree count) ----------------
__global__ void edge1_kernel(const int* __restrict__ src, const int* __restrict__ dst) {
    int e = blockIdx.x * 256 + threadIdx.x;
    if (e >= EE) return;
    int s = src[e], d = dst[e];
    float4 l0 = *(const float4*)(g_el1 + s * 8);
    float4 l1 = *(const float4*)(g_el1 + s * 8 + 4);
    float4 r0 = *(const float4*)(g_er1 + d * 8);
    float4 r1 = *(const float4*)(g_er1 + d * 8 + 4);
    float4 o0 = make_float4(leaky02(l0.x + r0.x), leaky02(l0.y + r0.y),
                            leaky02(l0.z + r0.z), leaky02(l0.w + r0.w));
    float4 o1 = make_float4(leaky02(l1.x + r1.x), leaky02(l1.y + r1.y),
                            leaky02(l1.z + r1.z), leaky02(l1.w + r1.w));
    *(float4*)(g_e1 + (size_t)e * 8) = o0;
    *(float4*)(g_e1 + (size_t)e * 8 + 4) = o1;
    atomicAdd(&g_cnt[d], 1);
}

// ---------------- exclusive scan of counts (single block) ----------------
__global__ void scan_kernel() {
    __shared__ int sh[1024];
    int tid = threadIdx.x;
    const int CH = (NN + 1023) / 1024;  // 30
    int lo = tid * CH, hi = min(lo + CH, NN);
    int s = 0;
    for (int i = lo; i < hi; i++) s += g_cnt[i];
    sh[tid] = s;
    __syncthreads();
    for (int off = 1; off < 1024; off <<= 1) {
        int v = (tid >= off) ? sh[tid - off] : 0;
        __syncthreads();
        sh[tid] += v;
        __syncthreads();
    }
    int run = sh[tid] - s;  // exclusive prefix
    for (int i = lo; i < hi; i++) { g_indptr[i] = run; run += g_cnt[i]; g_cnt[i] = 0; }
    if (tid == 1023) g_indptr[NN] = sh[1023];
}

__global__ void scatter_kernel(const int* __restrict__ src, const int* __restrict__ dst) {
    int e = blockIdx.x * 256 + threadIdx.x;
    if (e >= EE) return;
    int d = dst[e];
    int pos = g_indptr[d] + atomicAdd(&g_cnt[d], 1);
    g_csr_src[pos] = src[e];
    g_csr_eid[pos] = e;
}

// ---------------- layer-1 aggregation + residual + bias + ELU + LN + head-mean ----------------
__global__ void agg1_kernel(const float* __restrict__ b1) {
    int n = blockIdx.x;
    int tid = threadIdx.x;  // 256
    int h = tid >> 5, lane = tid & 31;
    __shared__ float s_m[8];
    __shared__ float s_w[32][8];
    __shared__ int s_src[32];
    __shared__ float s_out[8][64];
    int base = g_indptr[n];
    int deg = g_indptr[n + 1] - base;
    // pass 1: per-head max (warp h handles head h)
    float m = -INFINITY;
    for (int j = lane; j < deg; j += 32)
        m = fmaxf(m, g_e1[(size_t)g_csr_eid[base + j] * 8 + h]);
#pragma unroll
    for (int o = 16; o; o >>= 1) m = fmaxf(m, __shfl_xor_sync(0xffffffffu, m, o));
    if (lane == 0) s_m[h] = m;
    __syncthreads();
    // pass 2: weighted accumulation
    float acc0 = 0.f, acc1 = 0.f, wsum = 0.f;
    int c0 = lane * 2;
    for (int cs = 0; cs < deg; cs += 32) {
        int nc = min(32, deg - cs);
        if (tid < nc * 8) {
            int j = tid >> 3, hh = tid & 7;
            int eid = g_csr_eid[base + cs + j];
            s_w[j][hh] = __expf(g_e1[(size_t)eid * 8 + hh] - s_m[hh]);
        }
        if (tid < nc) s_src[tid] = g_csr_src[base + cs + tid];
        __syncthreads();
        for (int j = 0; j < nc; j++) {
            int s = s_src[j];
            float2 f = *(const float2*)(g_feat1 + (size_t)s * 512 + h * 64 + c0);
            float w = s_w[j][h];
            acc0 += w * f.x;
            acc1 += w * f.y;
            wsum += w;
        }
        __syncthreads();
    }
    float inv = wsum > 0.f ? 1.f / wsum : 0.f;
    float2 rr = *(const float2*)(g_res1 + (size_t)n * 512 + h * 64 + c0);
    float2 bb = *(const float2*)(b1 + h * 64 + c0);
    float v0 = acc0 * inv + rr.x + bb.x;
    float v1 = acc1 * inv + rr.y + bb.y;
    v0 = v0 > 0.f ? v0 : (__expf(v0) - 1.f);  // ELU
    v1 = v1 > 0.f ? v1 : (__expf(v1) - 1.f);
    // layernorm over 64 (per head), 2 values per lane
    float s = v0 + v1, ss = v0 * v0 + v1 * v1;
#pragma unroll
    for (int o = 16; o; o >>= 1) {
        s += __shfl_xor_sync(0xffffffffu, s, o);
        ss += __shfl_xor_sync(0xffffffffu, ss, o);
    }
    float mu = s * (1.f / 64.f);
    float var = ss * (1.f / 64.f) - mu * mu;
    float rs = rsqrtf(var + 1e-5f);
    s_out[h][c0] = (v0 - mu) * rs;
    s_out[h][c0 + 1] = (v1 - mu) * rs;
    __syncthreads();
    if (tid < 64) {
        float t = 0.f;
#pragma unroll
        for (int hh = 0; hh < 8; hh++) t += s_out[hh][tid];
        g_h2[(size_t)n * 64 + tid] = t * 0.125f;
    }
}

// ---------------- layer-2 attention ----------------
__global__ void attn2_kernel(const float* __restrict__ al, const float* __restrict__ ar) {
    int w = blockIdx.x * 8 + (threadIdx.x >> 5);
    if (w >= NN) return;
    int lane = threadIdx.x & 31;
    const float* f = g_feat2 + (size_t)w * 64;
    float a0 = f[lane] * al[lane] + f[lane + 32] * al[lane + 32];
    float b0 = f[lane] * ar[lane] + f[lane + 32] * ar[lane + 32];
#pragma unroll
    for (int o = 16; o; o >>= 1) {
        a0 += __shfl_xor_sync(0xffffffffu, a0, o);
        b0 += __shfl_xor_sync(0xffffffffu, b0, o);
    }
    if (lane == 0) { g_el2[w] = a0; g_er2[w] = b0; }
}

__global__ void edge2_kernel(const int* __restrict__ src, const int* __restrict__ dst) {
    int e = blockIdx.x * 256 + threadIdx.x;
    if (e >= EE) return;
    g_e2[e] = leaky02(g_el2[src[e]] + g_er2[dst[e]]);
}

// ---------------- layer-2 aggregation + identity residual + bias + ELU + LN ----------------
__global__ void agg2_kernel(const float* __restrict__ b2) {
    int n = blockIdx.x;
    int tid = threadIdx.x;  // 64
    __shared__ float s_w[64];
    __shared__ int s_src[64];
    __shared__ float s_red[2], s_red2[2];
    int base = g_indptr[n];
    int deg = g_indptr[n + 1] - base;
    float m = -INFINITY;
    for (int j = tid; j < deg; j += 64) m = fmaxf(m, g_e2[g_csr_eid[base + j]]);
#pragma unroll
    for (int o = 16; o; o >>= 1) m = fmaxf(m, __shfl_xor_sync(0xffffffffu, m, o));
    if ((tid & 31) == 0) s_red[tid >> 5] = m;
    __syncthreads();
    m = fmaxf(s_red[0], s_red[1]);
    float acc = 0.f, wsum = 0.f;
    for (int cs = 0; cs < deg; cs += 64) {
        int nc = min(64, deg - cs);
        __syncthreads();
        if (tid < nc) {
            int p = base + cs + tid;
            s_w[tid] = __expf(g_e2[g_csr_eid[p]] - m);
            s_src[tid] = g_csr_src[p];
        }
        __syncthreads();
        for (int j = 0; j < nc; j++) {
            float w = s_w[j];
            acc += w * g_feat2[(size_t)s_src[j] * 64 + tid];
            wsum += w;
        }
    }
    float inv = wsum > 0.f ? 1.f / wsum : 0.f;
    float v = acc * inv + g_h2[(size_t)n * 64 + tid] + b2[tid];
    v = v > 0.f ? v : (__expf(v) - 1.f);
    float s = v, ss = v * v;
#pragma unroll
    for (int o = 16; o; o >>= 1) {
        s += __shfl_xor_sync(0xffffffffu, s, o);
        ss += __shfl_xor_sync(0xffffffffu, ss, o);
    }
    __syncthreads();
    if ((tid & 31) == 0) { s_red[tid >> 5] = s; s_red2[tid >> 5] = ss; }
    __syncthreads();
    s = s_red[0] + s_red[1];
    ss = s_red2[0] + s_red2[1];
    float mu = s * (1.f / 64.f);
    float var = ss * (1.f / 64.f) - mu * mu;
    g_h3[(size_t)n * 64 + tid] = (v - mu) * rsqrtf(var + 1e-5f);
}

// ---------------- graph-level readout: hg = p0 + leaky(p1@gW1+gb1) + leaky(p2@gW2+gb2) ----------------
__global__ void hg_kernel(const float* __restrict__ gW1, const float* __restrict__ gb1,
                          const float* __restrict__ gW2, const float* __restrict__ gb2) {
    int g = blockIdx.x, c = threadIdx.x;  // 64 threads
    float a = gb1[c], b = gb2[c];
    for (int k = 0; k < 64; k++) {
        a += g_p1[g * 64 + k] * gW1[k * 64 + c];
        b += g_p2[g * 64 + k] * gW2[k * 64 + c];
    }
    a = a > 0.f ? a : 0.01f * a;
    b = b > 0.f ? b : 0.01f * b;
    g_hg[g * 64 + c] = g_p0[g * 64 + c] + a + b;
}

// ---------------- small FC: out[g,c] = (relu?)(in[g,:K] @ W[:,c] + b[c]) ----------------
__global__ void fc_small(const float* __restrict__ in, const float* __restrict__ W,
                         const float* __restrict__ b, float* __restrict__ out,
                         int K, int C, int do_relu) {
    int g = blockIdx.x, c = threadIdx.x;  // C threads
    float a = b[c];
    for (int k = 0; k < K; k++) a += in[g * K + k] * W[k * C + c];
    if (do_relu) a = fmaxf(a, 0.f);
    out[g * C + c] = a;
}

// ---------------- launch ----------------
extern "C" void kernel_launch(void* const* d_in, const int* in_sizes, int n_in,
                              void* d_out, int out_size) {
    const float* X     = (const float*)d_in[0];
    const int*   src   = (const int*)d_in[1];
    const int*   dst   = (const int*)d_in[2];
    const int*   gid   = (const int*)d_in[3];
    const float* projW = (const float*)d_in[4];
    const float* projb = (const float*)d_in[5];
    const float* fcW1  = (const float*)d_in[6];
    const float* al1   = (const float*)d_in[7];
    const float* ar1   = (const float*)d_in[8];
    const float* resW1 = (const float*)d_in[9];
    const float* b1    = (const float*)d_in[10];
    const float* fcW2  = (const float*)d_in[11];
    const float* al2   = (const float*)d_in[12];
    const float* ar2   = (const float*)d_in[13];
    const float* b2    = (const float*)d_in[14];
    const float* gW1   = (const float*)d_in[15];
    const float* gb1   = (const float*)d_in[16];
    const float* gW2   = (const float*)d_in[17];
    const float* gb2   = (const float*)d_in[18];
    const float* mW0   = (const float*)d_in[19];
    const float* mb0   = (const float*)d_in[20];
    const float* mW1   = (const float*)d_in[21];
    const float* mb1   = (const float*)d_in[22];
    const float* mW2   = (const float*)d_in[23];
    const float* mb2   = (const float*)d_in[24];
    float* out = (float*)d_out;

    // resolve scratch symbol addresses (pure address queries; capture-safe)
    float *p_h, *p_feat1, *p_res1, *p_h2, *p_feat2, *p_h3, *p_p0, *p_p1, *p_p2, *p_hg, *p_t0, *p_t1;
    cudaGetSymbolAddress((void**)&p_h, g_h);
    cudaGetSymbolAddress((void**)&p_feat1, g_feat1);
    cudaGetSymbolAddress((void**)&p_res1, g_res1);
    cudaGetSymbolAddress((void**)&p_h2, g_h2);
    cudaGetSymbolAddress((void**)&p_feat2, g_feat2);
    cudaGetSymbolAddress((void**)&p_h3, g_h3);
    cudaGetSymbolAddress((void**)&p_p0, g_p0);
    cudaGetSymbolAddress((void**)&p_p1, g_p1);
    cudaGetSymbolAddress((void**)&p_p2, g_p2);
    cudaGetSymbolAddress((void**)&p_hg, g_hg);
    cudaGetSymbolAddress((void**)&p_t0, g_t0);
    cudaGetSymbolAddress((void**)&p_t1, g_t1);

    const int EB = (EE + 255) / 256;
    const int RB = (NN + 63) / 64;
    const int PB = (NN + 255) / 256;

    zero_kernel<<<(NN + 255) / 256, 256>>>();
    // projection: h = X @ projW + projb
    gemm_k64<<<dim3(RB, 1), 256>>>(X, projW, projb, p_h, NN, 64);
    pool_kernel<<<PB, 64>>>(p_h, p_p0, gid);
    // layer-1 feature + residual GEMMs
    gemm_k64<<<dim3(RB, 8), 256>>>(p_h, fcW1, nullptr, p_feat1, NN, 512);
    gemm_k64<<<dim3(RB, 8), 256>>>(p_h, resW1, nullptr, p_res1, NN, 512);
    attn1_kernel<<<NN, 256>>>(al1, ar1);
    edge1_kernel<<<EB, 256>>>(src, dst);   // scores + in-degree counts
    scan_kernel<<<1, 1024>>>();            // CSR offsets
    scatter_kernel<<<EB, 256>>>(src, dst); // CSR fill
    agg1_kernel<<<NN, 256>>>(b1);          // softmax-agg + res + ELU + LN + head-mean
    pool_kernel<<<PB, 64>>>(p_h2, p_p1, gid);
    // layer 2
    gemm_k64<<<dim3(RB, 1), 256>>>(p_h2, fcW2, nullptr, p_feat2, NN, 64);
    attn2_kernel<<<(NN + 7) / 8, 256>>>(al2, ar2);
    edge2_kernel<<<EB, 256>>>(src, dst);
    agg2_kernel<<<NN, 64>>>(b2);
    pool_kernel<<<PB, 64>>>(p_h3, p_p2, gid);
    // readout + MLP head
    hg_kernel<<<GG, 64>>>(gW1, gb1, gW2, gb2);
    fc_small<<<GG, 256>>>(p_hg, mW0, mb0, p_t0, 64, 256, 1);
    fc_small<<<GG, 256>>>(p_t0, mW1, mb1, p_t1, 256, 256, 1);
    fc_small<<<GG, 256>>>(p_t1, mW2, mb2, out, 256, 256, 0);
}

// round 3
// speedup vs baseline: 1.0596x; 1.0596x over previous
#include <cuda_runtime.h>
#include <cuda_fp16.h>
#include <math.h>

#define NN 30000
#define EE 480000
#define GG 64
#define HFD 64
#define NHEADS 8
#define MLPD 256

// ---------------- scratch (static device memory) ----------------
__device__ float  g_h[NN * HFD];
__device__ float  g_feat1[NN * NHEADS * HFD];    // 61 MB fp32 (attn + nothing else)
__device__ __half g_feat1h[NN * NHEADS * HFD];   // 30 MB fp16 gather copy
__device__ float  g_res1[NN * NHEADS * HFD];
__device__ float  g_el1[NN * NHEADS];
__device__ float  g_er1[NN * NHEADS];
__device__ int    g_cnt[NN];
__device__ int    g_indptr[NN + 1];
__device__ int    g_csr_src[EE];
__device__ float  g_h2[NN * HFD];
__device__ float  g_feat2[NN * HFD];
__device__ __half g_feat2h[NN * HFD];
__device__ float  g_el2[NN];
__device__ float  g_er2[NN];
__device__ float  g_h3[NN * HFD];
__device__ float  g_p0[GG * HFD];
__device__ float  g_p1[GG * HFD];
__device__ float  g_p2[GG * HFD];
__device__ float  g_hg[GG * HFD];
__device__ float  g_t0[GG * MLPD];
__device__ float  g_t1[GG * MLPD];

// ---------------- f32x2 helpers ----------------
__device__ __forceinline__ void fma2(unsigned long long& d, unsigned long long a,
                                     unsigned long long b) {
    asm("fma.rn.f32x2 %0, %1, %2, %0;" : "+l"(d) : "l"(a), "l"(b));
}
__device__ __forceinline__ float2 unpk(unsigned long long v) {
    float2 r;
    asm("mov.b64 {%0,%1}, %2;" : "=f"(r.x), "=f"(r.y) : "l"(v));
    return r;
}

// ---------------- init ----------------
__global__ void zero_kernel() {
    int i = blockIdx.x * blockDim.x + threadIdx.x;
    if (i < NN) g_cnt[i] = 0;
    if (i < GG * HFD) { g_p0[i] = 0.f; g_p1[i] = 0.f; g_p2[i] = 0.f; }
}

// ---------------- GEMM via packed f32x2 FFMA: Out[nrows,ncols] = A[nrows,64]@W[64,ncols] (+bias)
// Block: 256 threads, tile 128 rows x 64 cols. Thread: 8 rows x 4 cols.
// K paired along even/odd (f32x2 partial sums) -> both operands are natural LDS.64.
__global__ __launch_bounds__(256, 2)
void gemm_t(const float* __restrict__ A, const float* __restrict__ W,
            const float* __restrict__ bias, float* __restrict__ Out,
            int nrows, int ncols) {
    __shared__ float sA[128 * 32];   // [row][k-chunk of 32]
    __shared__ float sW[64 * 34];    // transposed [col][k] padded to 34
    int r0 = blockIdx.x * 128;
    int c0 = blockIdx.y * 64;
    int tid = threadIdx.x;
    int rt = (tid >> 4) << 3;        // 8 rows
    int ct = tid & 15;               // cols ct, ct+16, ct+32, ct+48

    unsigned long long acc[8][4];
#pragma unroll
    for (int i = 0; i < 8; i++)
#pragma unroll
        for (int j = 0; j < 4; j++) acc[i][j] = 0ULL;

    for (int kc = 0; kc < 64; kc += 32) {
        // load A chunk: 128x32 floats = 1024 float4 -> 4 per thread
#pragma unroll
        for (int i = 0; i < 4; i++) {
            int idx = tid + i * 256;
            int r = idx >> 3, k4 = (idx & 7) << 2;
            float4 v = make_float4(0.f, 0.f, 0.f, 0.f);
            if (r0 + r < nrows) v = *(const float4*)(A + (size_t)(r0 + r) * 64 + kc + k4);
            *(float4*)(sA + r * 32 + k4) = v;
        }
        // load W chunk transposed: 32k x 64c -> sW[c][k]
#pragma unroll
        for (int i = 0; i < 2; i++) {
            int idx = tid + i * 256;       // 512 float4 slots
            int kw = idx >> 4, cw = (idx & 15) << 2;
            float4 v = *(const float4*)(W + (size_t)(kc + kw) * ncols + c0 + cw);
            sW[(cw + 0) * 34 + kw] = v.x;
            sW[(cw + 1) * 34 + kw] = v.y;
            sW[(cw + 2) * 34 + kw] = v.z;
            sW[(cw + 3) * 34 + kw] = v.w;
        }
        __syncthreads();
#pragma unroll 4
        for (int kp = 0; kp < 16; kp++) {
            unsigned long long w0 = *(const unsigned long long*)(sW + (ct +  0) * 34 + 2 * kp);
            unsigned long long w1 = *(const unsigned long long*)(sW + (ct + 16) * 34 + 2 * kp);
            unsigned long long w2 = *(const unsigned long long*)(sW + (ct + 32) * 34 + 2 * kp);
            unsigned long long w3 = *(const unsigned long long*)(sW + (ct + 48) * 34 + 2 * kp);
#pragma unroll
            for (int i = 0; i < 8; i++) {
                unsigned long long av = *(const unsigned long long*)(sA + (rt + i) * 32 + 2 * kp);
                fma2(acc[i][0], av, w0);
                fma2(acc[i][1], av, w1);
                fma2(acc[i][2], av, w2);
                fma2(acc[i][3], av, w3);
            }
        }
        __syncthreads();
    }
#pragma unroll
    for (int j = 0; j < 4; j++) {
        int c = c0 + ct + 16 * j;
        float bv = bias ? bias[c] : 0.f;
#pragma unroll
        for (int i = 0; i < 8; i++) {
            int r = r0 + rt + i;
            if (r < nrows) {
                float2 u = unpk(acc[i][j]);
                Out[(size_t)r * ncols + c] = u.x + u.y + bv;
            }
        }
    }
}

// ---------------- segment-sum pool by (sorted) graph_id ----------------
__global__ void pool_kernel(const float* __restrict__ x, float* __restrict__ out,
                            const int* __restrict__ gid) {
    int n0 = blockIdx.x * 256;
    int n1 = min(n0 + 256, NN);
    if (n0 >= NN) return;
    int c = threadIdx.x;  // 64
    int cur = gid[n0];
    float s = 0.f;
    for (int n = n0; n < n1; n++) {
        int g = gid[n];
        if (g != cur) { atomicAdd(&out[cur * HFD + c], s); s = 0.f; cur = g; }
        s += x[(size_t)n * HFD + c];
    }
    atomicAdd(&out[cur * HFD + c], s);
}

// ---------------- layer-1 attention dot products + fp16 conversion ----------------
__global__ void attn1_kernel(const float* __restrict__ al, const float* __restrict__ ar) {
    int n = blockIdx.x;
    int h = threadIdx.x >> 5, lane = threadIdx.x & 31;
    size_t off = (size_t)n * 512 + h * 64 + 2 * lane;
    float2 f = *(const float2*)(g_feat1 + off);
    float2 a = *(const float2*)(al + h * 64 + 2 * lane);
    float2 b = *(const float2*)(ar + h * 64 + 2 * lane);
    *(__half2*)(g_feat1h + off) = __floats2half2_rn(f.x, f.y);
    float a0 = f.x * a.x + f.y * a.y;
    float b0 = f.x * b.x + f.y * b.y;
#pragma unroll
    for (int o = 16; o; o >>= 1) {
        a0 += __shfl_xor_sync(0xffffffffu, a0, o);
        b0 += __shfl_xor_sync(0xffffffffu, b0, o);
    }
    if (lane == 0) { g_el1[n * 8 + h] = a0; g_er1[n * 8 + h] = b0; }
}

__device__ __forceinline__ float leaky02(float v) { return v > 0.f ? v : 0.2f * v; }

// ---------------- in-degree count ----------------
__global__ void count_kernel(const int* __restrict__ dst) {
    int e = blockIdx.x * 256 + threadIdx.x;
    if (e < EE) atomicAdd(&g_cnt[dst[e]], 1);
}

// ---------------- exclusive scan of counts (single block) ----------------
__global__ void scan_kernel() {
    __shared__ int sh[1024];
    int tid = threadIdx.x;
    const int CH = (NN + 1023) / 1024;
    int lo = tid * CH, hi = min(lo + CH, NN);
    int s = 0;
    for (int i = lo; i < hi; i++) s += g_cnt[i];
    sh[tid] = s;
    __syncthreads();
    for (int off = 1; off < 1024; off <<= 1) {
        int v = (tid >= off) ? sh[tid - off] : 0;
        __syncthreads();
        sh[tid] += v;
        __syncthreads();
    }
    int run = sh[tid] - s;
    for (int i = lo; i < hi; i++) { g_indptr[i] = run; run += g_cnt[i]; g_cnt[i] = 0; }
    if (tid == 1023) g_indptr[NN] = sh[1023];
}

__global__ void scatter_kernel(const int* __restrict__ src, const int* __restrict__ dst) {
    int e = blockIdx.x * 256 + threadIdx.x;
    if (e >= EE) return;
    int d = dst[e];
    int pos = g_indptr[d] + atomicAdd(&g_cnt[d], 1);
    g_csr_src[pos] = src[e];
}

// ---------------- layer-1: softmax-agg + residual + bias + ELU + LN + head-mean ----------------
__global__ void agg1_kernel(const float* __restrict__ b1) {
    int n = blockIdx.x;
    int tid = threadIdx.x;  // 256
    int h = tid >> 5, lane = tid & 31;
    __shared__ float s_w[32][8];
    __shared__ int s_src[32];
    __shared__ float s_er[8];
    __shared__ float s_out[8][64];
    int base = g_indptr[n];
    int deg = g_indptr[n + 1] - base;
    if (tid < 8) s_er[tid] = g_er1[n * 8 + tid];

    float acc0 = 0.f, acc1 = 0.f, wsum = 0.f;
    int c0 = lane * 2;
    for (int cs = 0; cs < deg; cs += 32) {
        int nc = min(32, deg - cs);
        __syncthreads();
        if (tid < nc * 8) {
            int j = tid >> 3, hh = tid & 7;
            int s = g_csr_src[base + cs + j];
            if ((tid & 7) == 0) s_src[j] = s;
            s_w[j][hh] = __expf(leaky02(g_el1[s * 8 + hh] + s_er[hh]));
        }
        __syncthreads();
        for (int j = 0; j < nc; j++) {
            int s = s_src[j];
            __half2 hf = *(const __half2*)(g_feat1h + (size_t)s * 512 + h * 64 + c0);
            float2 f = __half22float2(hf);
            float w = s_w[j][h];
            acc0 += w * f.x;
            acc1 += w * f.y;
            wsum += w;
        }
    }
    float inv = wsum > 0.f ? 1.f / wsum : 0.f;
    float2 rr = *(const float2*)(g_res1 + (size_t)n * 512 + h * 64 + c0);
    float2 bb = *(const float2*)(b1 + h * 64 + c0);
    float v0 = acc0 * inv + rr.x + bb.x;
    float v1 = acc1 * inv + rr.y + bb.y;
    v0 = v0 > 0.f ? v0 : (__expf(v0) - 1.f);
    v1 = v1 > 0.f ? v1 : (__expf(v1) - 1.f);
    float s = v0 + v1, ss = v0 * v0 + v1 * v1;
#pragma unroll
    for (int o = 16; o; o >>= 1) {
        s += __shfl_xor_sync(0xffffffffu, s, o);
        ss += __shfl_xor_sync(0xffffffffu, ss, o);
    }
    float mu = s * (1.f / 64.f);
    float var = ss * (1.f / 64.f) - mu * mu;
    float rs = rsqrtf(var + 1e-5f);
    s_out[h][c0] = (v0 - mu) * rs;
    s_out[h][c0 + 1] = (v1 - mu) * rs;
    __syncthreads();
    if (tid < 64) {
        float t = 0.f;
#pragma unroll
        for (int hh = 0; hh < 8; hh++) t += s_out[hh][tid];
        g_h2[(size_t)n * 64 + tid] = t * 0.125f;
    }
}

// ---------------- layer-2 attention + fp16 conversion ----------------
__global__ void attn2_kernel(const float* __restrict__ al, const float* __restrict__ ar) {
    int w = blockIdx.x * 8 + (threadIdx.x >> 5);
    if (w >= NN) return;
    int lane = threadIdx.x & 31;
    size_t off = (size_t)w * 64 + 2 * lane;
    float2 f = *(const float2*)(g_feat2 + off);
    float2 a = *(const float2*)(al + 2 * lane);
    float2 b = *(const float2*)(ar + 2 * lane);
    *(__half2*)(g_feat2h + off) = __floats2half2_rn(f.x, f.y);
    float a0 = f.x * a.x + f.y * a.y;
    float b0 = f.x * b.x + f.y * b.y;
#pragma unroll
    for (int o = 16; o; o >>= 1) {
        a0 += __shfl_xor_sync(0xffffffffu, a0, o);
        b0 += __shfl_xor_sync(0xffffffffu, b0, o);
    }
    if (lane == 0) { g_el2[w] = a0; g_er2[w] = b0; }
}

// ---------------- layer-2: softmax-agg + identity residual + bias + ELU + LN ----------------
__global__ void agg2_kernel(const float* __restrict__ b2) {
    int n = blockIdx.x;
    int tid = threadIdx.x;  // 64
    __shared__ float s_w[64];
    __shared__ int s_src[64];
    __shared__ float s_red[2], s_red2[2];
    int base = g_indptr[n];
    int deg = g_indptr[n + 1] - base;
    float er = g_er2[n];
    float acc = 0.f, wsum = 0.f;
    for (int cs = 0; cs < deg; cs += 64) {
        int nc = min(64, deg - cs);
        __syncthreads();
        if (tid < nc) {
            int s = g_csr_src[base + cs + tid];
            s_src[tid] = s;
            s_w[tid] = __expf(leaky02(g_el2[s] + er));
        }
        __syncthreads();
        for (int j = 0; j < nc; j++) {
            float w = s_w[j];
            acc += w * __half2float(g_feat2h[(size_t)s_src[j] * 64 + tid]);
            wsum += w;
        }
    }
    float inv = wsum > 0.f ? 1.f / wsum : 0.f;
    float v = acc * inv + g_h2[(size_t)n * 64 + tid] + b2[tid];
    v = v > 0.f ? v : (__expf(v) - 1.f);
    float s = v, ss = v * v;
#pragma unroll
    for (int o = 16; o; o >>= 1) {
        s += __shfl_xor_sync(0xffffffffu, s, o);
        ss += __shfl_xor_sync(0xffffffffu, ss, o);
    }
    __syncthreads();
    if ((tid & 31) == 0) { s_red[tid >> 5] = s; s_red2[tid >> 5] = ss; }
    __syncthreads();
    s = s_red[0] + s_red[1];
    ss = s_red2[0] + s_red2[1];
    float mu = s * (1.f / 64.f);
    float var = ss * (1.f / 64.f) - mu * mu;
    g_h3[(size_t)n * 64 + tid] = (v - mu) * rsqrtf(var + 1e-5f);
}

// ---------------- graph-level readout ----------------
__global__ void hg_kernel(const float* __restrict__ gW1, const float* __restrict__ gb1,
                          const float* __restrict__ gW2, const float* __restrict__ gb2) {
    int g = blockIdx.x, c = threadIdx.x;  // 64
    float a = gb1[c], b = gb2[c];
    for (int k = 0; k < 64; k++) {
        a += g_p1[g * 64 + k] * gW1[k * 64 + c];
        b += g_p2[g * 64 + k] * gW2[k * 64 + c];
    }
    a = a > 0.f ? a : 0.01f * a;
    b = b > 0.f ? b : 0.01f * b;
    g_hg[g * 64 + c] = g_p0[g * 64 + c] + a + b;
}

// ---------------- small FC ----------------
__global__ void fc_small(const float* __restrict__ in, const float* __restrict__ W,
                         const float* __restrict__ b, float* __restrict__ out,
                         int K, int C, int do_relu) {
    int g = blockIdx.x, c = threadIdx.x;
    float a = b[c];
    for (int k = 0; k < K; k++) a += in[g * K + k] * W[k * C + c];
    if (do_relu) a = fmaxf(a, 0.f);
    out[g * C + c] = a;
}

// ---------------- launch ----------------
extern "C" void kernel_launch(void* const* d_in, const int* in_sizes, int n_in,
                              void* d_out, int out_size) {
    const float* X     = (const float*)d_in[0];
    const int*   src   = (const int*)d_in[1];
    const int*   dst   = (const int*)d_in[2];
    const int*   gid   = (const int*)d_in[3];
    const float* projW = (const float*)d_in[4];
    const float* projb = (const float*)d_in[5];
    const float* fcW1  = (const float*)d_in[6];
    const float* al1   = (const float*)d_in[7];
    const float* ar1   = (const float*)d_in[8];
    const float* resW1 = (const float*)d_in[9];
    const float* b1    = (const float*)d_in[10];
    const float* fcW2  = (const float*)d_in[11];
    const float* al2   = (const float*)d_in[12];
    const float* ar2   = (const float*)d_in[13];
    const float* b2    = (const float*)d_in[14];
    const float* gW1   = (const float*)d_in[15];
    const float* gb1   = (const float*)d_in[16];
    const float* gW2   = (const float*)d_in[17];
    const float* gb2   = (const float*)d_in[18];
    const float* mW0   = (const float*)d_in[19];
    const float* mb0   = (const float*)d_in[20];
    const float* mW1   = (const float*)d_in[21];
    const float* mb1   = (const float*)d_in[22];
    const float* mW2   = (const float*)d_in[23];
    const float* mb2   = (const float*)d_in[24];
    float* out = (float*)d_out;

    float *p_h, *p_feat1, *p_res1, *p_h2, *p_feat2, *p_h3, *p_p0, *p_p1, *p_p2, *p_hg, *p_t0, *p_t1;
    cudaGetSymbolAddress((void**)&p_h, g_h);
    cudaGetSymbolAddress((void**)&p_feat1, g_feat1);
    cudaGetSymbolAddress((void**)&p_res1, g_res1);
    cudaGetSymbolAddress((void**)&p_h2, g_h2);
    cudaGetSymbolAddress((void**)&p_feat2, g_feat2);
    cudaGetSymbolAddress((void**)&p_h3, g_h3);
    cudaGetSymbolAddress((void**)&p_p0, g_p0);
    cudaGetSymbolAddress((void**)&p_p1, g_p1);
    cudaGetSymbolAddress((void**)&p_p2, g_p2);
    cudaGetSymbolAddress((void**)&p_hg, g_hg);
    cudaGetSymbolAddress((void**)&p_t0, g_t0);
    cudaGetSymbolAddress((void**)&p_t1, g_t1);

    const int EB = (EE + 255) / 256;
    const int RB = (NN + 127) / 128;   // 235
    const int PB = (NN + 255) / 256;

    zero_kernel<<<(NN + 255) / 256, 256>>>();
    count_kernel<<<EB, 256>>>(dst);
    scan_kernel<<<1, 1024>>>();
    scatter_kernel<<<EB, 256>>>(src, dst);
    // projection: h = X @ projW + projb
    gemm_t<<<dim3(RB, 1), 256>>>(X, projW, projb, p_h, NN, 64);
    pool_kernel<<<PB, 64>>>(p_h, p_p0, gid);
    // layer-1 feature + residual GEMMs
    gemm_t<<<dim3(RB, 8), 256>>>(p_h, fcW1, nullptr, p_feat1, NN, 512);
    gemm_t<<<dim3(RB, 8), 256>>>(p_h, resW1, nullptr, p_res1, NN, 512);
    attn1_kernel<<<NN, 256>>>(al1, ar1);
    agg1_kernel<<<NN, 256>>>(b1);
    pool_kernel<<<PB, 64>>>(p_h2, p_p1, gid);
    // layer 2
    gemm_t<<<dim3(RB, 1), 256>>>(p_h2, fcW2, nullptr, p_feat2, NN, 64);
    attn2_kernel<<<(NN + 7) / 8, 256>>>(al2, ar2);
    agg2_kernel<<<NN, 64>>>(b2);
    pool_kernel<<<PB, 64>>>(p_h3, p_p2, gid);
    // readout + MLP head
    hg_kernel<<<GG, 64>>>(gW1, gb1, gW2, gb2);
    fc_small<<<GG, 256>>>(p_hg, mW0, mb0, p_t0, 64, 256, 1);
    fc_small<<<GG, 256>>>(p_t0, mW1, mb1, p_t1, 256, 256, 1);
    fc_small<<<GG, 256>>>(p_t1, mW2, mb2, out, 256, 256, 0);
}

// round 4
// speedup vs baseline: 1.1623x; 1.0969x over previous
#include <cuda_runtime.h>
#include <cuda_fp16.h>
#include <math.h>

#define NN 30000
#define EE 480000
#define GG 64
#define HFD 64
#define NHEADS 8
#define MLPD 256

// ---------------- scratch (static device memory) ----------------
__device__ float  g_h[NN * HFD];
__device__ __half g_feat1h[NN * NHEADS * HFD];   // 30 MB fp16
__device__ __half g_res1h[NN * NHEADS * HFD];    // 30 MB fp16
__device__ float  g_el1[NN * NHEADS];
__device__ float  g_er1[NN * NHEADS];
__device__ int    g_cnt[NN];
__device__ int    g_indptr[NN + 1];
__device__ int    g_csr_src[EE];
__device__ float  g_h2[NN * HFD];
__device__ __half g_feat2h[NN * HFD];
__device__ float  g_el2[NN];
__device__ float  g_er2[NN];
__device__ float  g_h3[NN * HFD];
__device__ float  g_p0[GG * HFD];
__device__ float  g_p1[GG * HFD];
__device__ float  g_p2[GG * HFD];
__device__ float  g_hg[GG * HFD];
__device__ float  g_t0[GG * MLPD];
__device__ float  g_t1[GG * MLPD];

// ---------------- f32x2 helpers ----------------
__device__ __forceinline__ void fma2(unsigned long long& d, unsigned long long a,
                                     unsigned long long b) {
    asm("fma.rn.f32x2 %0, %1, %2, %0;" : "+l"(d) : "l"(a), "l"(b));
}
__device__ __forceinline__ float2 unpk(unsigned long long v) {
    float2 r;
    asm("mov.b64 {%0,%1}, %2;" : "=f"(r.x), "=f"(r.y) : "l"(v));
    return r;
}

// ---------------- init ----------------
__global__ void zero_kernel() {
    int i = blockIdx.x * blockDim.x + threadIdx.x;
    if (i < NN) g_cnt[i] = 0;
    if (i < GG * HFD) { g_p0[i] = 0.f; g_p1[i] = 0.f; g_p2[i] = 0.f; }
}

// ---------------- shared GEMM mainloop (f32x2) ----------------
// Block: 256 threads, tile 128 rows x 64 cols. Thread: 8 rows x 4 cols
// (cols ct, ct+16, ct+32, ct+48). K paired even/odd -> natural LDS.64.
__device__ __forceinline__ void gemm_core(const float* __restrict__ A,
                                          const float* __restrict__ W,
                                          int nrows, int ncols, int r0, int c0,
                                          unsigned long long (&acc)[8][4],
                                          float* sA, float* sW) {
    int tid = threadIdx.x;
    int rt = (tid >> 4) << 3;
    int ct = tid & 15;
#pragma unroll
    for (int i = 0; i < 8; i++)
#pragma unroll
        for (int j = 0; j < 4; j++) acc[i][j] = 0ULL;
    for (int kc = 0; kc < 64; kc += 32) {
#pragma unroll
        for (int i = 0; i < 4; i++) {
            int idx = tid + i * 256;
            int r = idx >> 3, k4 = (idx & 7) << 2;
            float4 v = make_float4(0.f, 0.f, 0.f, 0.f);
            if (r0 + r < nrows) v = *(const float4*)(A + (size_t)(r0 + r) * 64 + kc + k4);
            *(float4*)(sA + r * 32 + k4) = v;
        }
#pragma unroll
        for (int i = 0; i < 2; i++) {
            int idx = tid + i * 256;
            int kw = idx >> 4, cw = (idx & 15) << 2;
            float4 v = *(const float4*)(W + (size_t)(kc + kw) * ncols + c0 + cw);
            sW[(cw + 0) * 34 + kw] = v.x;
            sW[(cw + 1) * 34 + kw] = v.y;
            sW[(cw + 2) * 34 + kw] = v.z;
            sW[(cw + 3) * 34 + kw] = v.w;
        }
        __syncthreads();
#pragma unroll 4
        for (int kp = 0; kp < 16; kp++) {
            unsigned long long w0 = *(const unsigned long long*)(sW + (ct +  0) * 34 + 2 * kp);
            unsigned long long w1 = *(const unsigned long long*)(sW + (ct + 16) * 34 + 2 * kp);
            unsigned long long w2 = *(const unsigned long long*)(sW + (ct + 32) * 34 + 2 * kp);
            unsigned long long w3 = *(const unsigned long long*)(sW + (ct + 48) * 34 + 2 * kp);
#pragma unroll
            for (int i = 0; i < 8; i++) {
                unsigned long long av = *(const unsigned long long*)(sA + (rt + i) * 32 + 2 * kp);
                fma2(acc[i][0], av, w0);
                fma2(acc[i][1], av, w1);
                fma2(acc[i][2], av, w2);
                fma2(acc[i][3], av, w3);
            }
        }
        __syncthreads();
    }
}

// ---------------- fp32-out GEMM (projection) ----------------
__global__ __launch_bounds__(256, 2)
void gemm_t(const float* __restrict__ A, const float* __restrict__ W,
            const float* __restrict__ bias, float* __restrict__ Out,
            int nrows, int ncols) {
    __shared__ float sA[128 * 32];
    __shared__ float sW[64 * 34];
    int r0 = blockIdx.x * 128, c0 = blockIdx.y * 64;
    int tid = threadIdx.x;
    int rt = (tid >> 4) << 3, ct = tid & 15;
    unsigned long long acc[8][4];
    gemm_core(A, W, nrows, ncols, r0, c0, acc, sA, sW);
#pragma unroll
    for (int j = 0; j < 4; j++) {
        int c = c0 + ct + 16 * j;
        float bv = bias ? bias[c] : 0.f;
#pragma unroll
        for (int i = 0; i < 8; i++) {
            int r = r0 + rt + i;
            if (r < nrows) {
                float2 u = unpk(acc[i][j]);
                Out[(size_t)r * ncols + c] = u.x + u.y + bv;
            }
        }
    }
}

// ---------------- fp16-out GEMM with fused attention dots ----------------
// If al != null: computes el[r*hstride+head], er[r*hstride+head] where
// head = c0/64 (weight cols are grouped per head so al index == global col c).
__global__ __launch_bounds__(256, 2)
void gemm_h(const float* __restrict__ A, const float* __restrict__ W,
            __half* __restrict__ OutH,
            float* __restrict__ el, float* __restrict__ er,
            const float* __restrict__ al, const float* __restrict__ ar,
            int nrows, int ncols, int hstride) {
    __shared__ float sA[128 * 32];
    __shared__ float sW[64 * 34];
    int r0 = blockIdx.x * 128, c0 = blockIdx.y * 64;
    int tid = threadIdx.x;
    int rt = (tid >> 4) << 3, ct = tid & 15;
    unsigned long long acc[8][4];
    gemm_core(A, W, nrows, ncols, r0, c0, acc, sA, sW);

    float elp[8], erp[8];
#pragma unroll
    for (int i = 0; i < 8; i++) { elp[i] = 0.f; erp[i] = 0.f; }
#pragma unroll
    for (int j = 0; j < 4; j++) {
        int c = c0 + ct + 16 * j;
        float av = al ? al[c] : 0.f;
        float bv = al ? ar[c] : 0.f;
#pragma unroll
        for (int i = 0; i < 8; i++) {
            int r = r0 + rt + i;
            float2 u = unpk(acc[i][j]);
            float val = u.x + u.y;
            if (r < nrows) OutH[(size_t)r * ncols + c] = __float2half_rn(val);
            elp[i] += val * av;
            erp[i] += val * bv;
        }
    }
    if (al) {
        // reduce over the 16 threads sharing the same rows (xor within half-warp)
#pragma unroll
        for (int o = 1; o < 16; o <<= 1) {
#pragma unroll
            for (int i = 0; i < 8; i++) {
                elp[i] += __shfl_xor_sync(0xffffffffu, elp[i], o);
                erp[i] += __shfl_xor_sync(0xffffffffu, erp[i], o);
            }
        }
        if (ct == 0) {
            int head = c0 >> 6;
#pragma unroll
            for (int i = 0; i < 8; i++) {
                int r = r0 + rt + i;
                if (r < nrows) {
                    el[(size_t)r * hstride + head] = elp[i];
                    er[(size_t)r * hstride + head] = erp[i];
                }
            }
        }
    }
}

// ---------------- segment-sum pool by (sorted) graph_id ----------------
__global__ void pool_kernel(const float* __restrict__ x, float* __restrict__ out,
                            const int* __restrict__ gid) {
    int n0 = blockIdx.x * 256;
    int n1 = min(n0 + 256, NN);
    if (n0 >= NN) return;
    int c = threadIdx.x;  // 64
    int cur = gid[n0];
    float s = 0.f;
    for (int n = n0; n < n1; n++) {
        int g = gid[n];
        if (g != cur) { atomicAdd(&out[cur * HFD + c], s); s = 0.f; cur = g; }
        s += x[(size_t)n * HFD + c];
    }
    atomicAdd(&out[cur * HFD + c], s);
}

__device__ __forceinline__ float leaky02(float v) { return v > 0.f ? v : 0.2f * v; }

// ---------------- CSR build ----------------
__global__ void count_kernel(const int* __restrict__ dst) {
    int e = blockIdx.x * 256 + threadIdx.x;
    if (e < EE) atomicAdd(&g_cnt[dst[e]], 1);
}

__global__ void scan_kernel() {
    __shared__ int sh[1024];
    int tid = threadIdx.x;
    const int CH = (NN + 1023) / 1024;
    int lo = tid * CH, hi = min(lo + CH, NN);
    int s = 0;
    for (int i = lo; i < hi; i++) s += g_cnt[i];
    sh[tid] = s;
    __syncthreads();
    for (int off = 1; off < 1024; off <<= 1) {
        int v = (tid >= off) ? sh[tid - off] : 0;
        __syncthreads();
        sh[tid] += v;
        __syncthreads();
    }
    int run = sh[tid] - s;
    for (int i = lo; i < hi; i++) { g_indptr[i] = run; run += g_cnt[i]; g_cnt[i] = 0; }
    if (tid == 1023) g_indptr[NN] = sh[1023];
}

__global__ void scatter_kernel(const int* __restrict__ src, const int* __restrict__ dst) {
    int e = blockIdx.x * 256 + threadIdx.x;
    if (e >= EE) return;
    int d = dst[e];
    int pos = g_indptr[d] + atomicAdd(&g_cnt[d], 1);
    g_csr_src[pos] = src[e];
}

// ---------------- layer-1: softmax-agg + residual + bias + ELU + LN + head-mean ----------------
__global__ void agg1_kernel(const float* __restrict__ b1) {
    int n = blockIdx.x;
    int tid = threadIdx.x;  // 256
    int h = tid >> 5, lane = tid & 31;
    __shared__ float s_w[32][8];
    __shared__ int s_src[32];
    __shared__ float s_er[8];
    __shared__ float s_out[8][64];
    int base = g_indptr[n];
    int deg = g_indptr[n + 1] - base;
    if (tid < 8) s_er[tid] = g_er1[n * 8 + tid];

    float acc0 = 0.f, acc1 = 0.f, wsum = 0.f;
    int c0 = lane * 2;
    for (int cs = 0; cs < deg; cs += 32) {
        int nc = min(32, deg - cs);
        __syncthreads();
        if (tid < nc * 8) {
            int j = tid >> 3, hh = tid & 7;
            int s = g_csr_src[base + cs + j];
            if ((tid & 7) == 0) s_src[j] = s;
            s_w[j][hh] = __expf(leaky02(g_el1[s * 8 + hh] + s_er[hh]));
        }
        __syncthreads();
#pragma unroll 4
        for (int j = 0; j < nc; j++) {
            int s = s_src[j];
            __half2 hf = *(const __half2*)(g_feat1h + (size_t)s * 512 + h * 64 + c0);
            float2 f = __half22float2(hf);
            float w = s_w[j][h];
            acc0 += w * f.x;
            acc1 += w * f.y;
            wsum += w;
        }
    }
    float inv = wsum > 0.f ? 1.f / wsum : 0.f;
    float2 rr = __half22float2(*(const __half2*)(g_res1h + (size_t)n * 512 + h * 64 + c0));
    float2 bb = *(const float2*)(b1 + h * 64 + c0);
    float v0 = acc0 * inv + rr.x + bb.x;
    float v1 = acc1 * inv + rr.y + bb.y;
    v0 = v0 > 0.f ? v0 : (__expf(v0) - 1.f);
    v1 = v1 > 0.f ? v1 : (__expf(v1) - 1.f);
    float s = v0 + v1, ss = v0 * v0 + v1 * v1;
#pragma unroll
    for (int o = 16; o; o >>= 1) {
        s += __shfl_xor_sync(0xffffffffu, s, o);
        ss += __shfl_xor_sync(0xffffffffu, ss, o);
    }
    float mu = s * (1.f / 64.f);
    float var = ss * (1.f / 64.f) - mu * mu;
    float rs = rsqrtf(var + 1e-5f);
    s_out[h][c0] = (v0 - mu) * rs;
    s_out[h][c0 + 1] = (v1 - mu) * rs;
    __syncthreads();
    if (tid < 64) {
        float t = 0.f;
#pragma unroll
        for (int hh = 0; hh < 8; hh++) t += s_out[hh][tid];
        g_h2[(size_t)n * 64 + tid] = t * 0.125f;
    }
}

// ---------------- layer-2: softmax-agg + identity residual + bias + ELU + LN ----------------
__global__ void agg2_kernel(const float* __restrict__ b2) {
    int n = blockIdx.x;
    int tid = threadIdx.x;  // 64
    __shared__ float s_w[64];
    __shared__ int s_src[64];
    __shared__ float s_red[2], s_red2[2];
    int base = g_indptr[n];
    int deg = g_indptr[n + 1] - base;
    float er = g_er2[n];
    float acc = 0.f, wsum = 0.f;
    for (int cs = 0; cs < deg; cs += 64) {
        int nc = min(64, deg - cs);
        __syncthreads();
        if (tid < nc) {
            int s = g_csr_src[base + cs + tid];
            s_src[tid] = s;
            s_w[tid] = __expf(leaky02(g_el2[s] + er));
        }
        __syncthreads();
#pragma unroll 4
        for (int j = 0; j < nc; j++) {
            float w = s_w[j];
            acc += w * __half2float(g_feat2h[(size_t)s_src[j] * 64 + tid]);
            wsum += w;
        }
    }
    float inv = wsum > 0.f ? 1.f / wsum : 0.f;
    float v = acc * inv + g_h2[(size_t)n * 64 + tid] + b2[tid];
    v = v > 0.f ? v : (__expf(v) - 1.f);
    float s = v, ss = v * v;
#pragma unroll
    for (int o = 16; o; o >>= 1) {
        s += __shfl_xor_sync(0xffffffffu, s, o);
        ss += __shfl_xor_sync(0xffffffffu, ss, o);
    }
    __syncthreads();
    if ((tid & 31) == 0) { s_red[tid >> 5] = s; s_red2[tid >> 5] = ss; }
    __syncthreads();
    s = s_red[0] + s_red[1];
    ss = s_red2[0] + s_red2[1];
    float mu = s * (1.f / 64.f);
    float var = ss * (1.f / 64.f) - mu * mu;
    g_h3[(size_t)n * 64 + tid] = (v - mu) * rsqrtf(var + 1e-5f);
}

// ---------------- graph-level readout ----------------
__global__ void hg_kernel(const float* __restrict__ gW1, const float* __restrict__ gb1,
                          const float* __restrict__ gW2, const float* __restrict__ gb2) {
    int g = blockIdx.x, c = threadIdx.x;  // 64
    float a = gb1[c], b = gb2[c];
    for (int k = 0; k < 64; k++) {
        a += g_p1[g * 64 + k] * gW1[k * 64 + c];
        b += g_p2[g * 64 + k] * gW2[k * 64 + c];
    }
    a = a > 0.f ? a : 0.01f * a;
    b = b > 0.f ? b : 0.01f * b;
    g_hg[g * 64 + c] = g_p0[g * 64 + c] + a + b;
}

// ---------------- small FC ----------------
__global__ void fc_small(const float* __restrict__ in, const float* __restrict__ W,
                         const float* __restrict__ b, float* __restrict__ out,
                         int K, int C, int do_relu) {
    int g = blockIdx.x, c = threadIdx.x;
    float a = b[c];
    for (int k = 0; k < K; k++) a += in[g * K + k] * W[k * C + c];
    if (do_relu) a = fmaxf(a, 0.f);
    out[g * C + c] = a;
}

// ---------------- launch ----------------
extern "C" void kernel_launch(void* const* d_in, const int* in_sizes, int n_in,
                              void* d_out, int out_size) {
    const float* X     = (const float*)d_in[0];
    const int*   src   = (const int*)d_in[1];
    const int*   dst   = (const int*)d_in[2];
    const int*   gid   = (const int*)d_in[3];
    const float* projW = (const float*)d_in[4];
    const float* projb = (const float*)d_in[5];
    const float* fcW1  = (const float*)d_in[6];
    const float* al1   = (const float*)d_in[7];
    const float* ar1   = (const float*)d_in[8];
    const float* resW1 = (const float*)d_in[9];
    const float* b1    = (const float*)d_in[10];
    const float* fcW2  = (const float*)d_in[11];
    const float* al2   = (const float*)d_in[12];
    const float* ar2   = (const float*)d_in[13];
    const float* b2    = (const float*)d_in[14];
    const float* gW1   = (const float*)d_in[15];
    const float* gb1   = (const float*)d_in[16];
    const float* gW2   = (const float*)d_in[17];
    const float* gb2   = (const float*)d_in[18];
    const float* mW0   = (const float*)d_in[19];
    const float* mb0   = (const float*)d_in[20];
    const float* mW1   = (const float*)d_in[21];
    const float* mb1   = (const float*)d_in[22];
    const float* mW2   = (const float*)d_in[23];
    const float* mb2   = (const float*)d_in[24];
    float* out = (float*)d_out;

    float *p_h, *p_h2, *p_h3, *p_p0, *p_p1, *p_p2, *p_hg, *p_t0, *p_t1;
    float *p_el1, *p_er1, *p_el2, *p_er2;
    __half *p_feat1h, *p_res1h, *p_feat2h;
    cudaGetSymbolAddress((void**)&p_h, g_h);
    cudaGetSymbolAddress((void**)&p_feat1h, g_feat1h);
    cudaGetSymbolAddress((void**)&p_res1h, g_res1h);
    cudaGetSymbolAddress((void**)&p_el1, g_el1);
    cudaGetSymbolAddress((void**)&p_er1, g_er1);
    cudaGetSymbolAddress((void**)&p_h2, g_h2);
    cudaGetSymbolAddress((void**)&p_feat2h, g_feat2h);
    cudaGetSymbolAddress((void**)&p_el2, g_el2);
    cudaGetSymbolAddress((void**)&p_er2, g_er2);
    cudaGetSymbolAddress((void**)&p_h3, g_h3);
    cudaGetSymbolAddress((void**)&p_p0, g_p0);
    cudaGetSymbolAddress((void**)&p_p1, g_p1);
    cudaGetSymbolAddress((void**)&p_p2, g_p2);
    cudaGetSymbolAddress((void**)&p_hg, g_hg);
    cudaGetSymbolAddress((void**)&p_t0, g_t0);
    cudaGetSymbolAddress((void**)&p_t1, g_t1);

    const int EB = (EE + 255) / 256;
    const int RB = (NN + 127) / 128;
    const int PB = (NN + 255) / 256;

    zero_kernel<<<(NN + 255) / 256, 256>>>();
    count_kernel<<<EB, 256>>>(dst);
    scan_kernel<<<1, 1024>>>();
    scatter_kernel<<<EB, 256>>>(src, dst);
    // projection (fp32 out, needed as GEMM input + pool)
    gemm_t<<<dim3(RB, 1), 256>>>(X, projW, projb, p_h, NN, 64);
    pool_kernel<<<PB, 64>>>(p_h, p_p0, gid);
    // layer-1: feature GEMM with fused el/er + fp16 store; residual GEMM fp16
    gemm_h<<<dim3(RB, 8), 256>>>(p_h, fcW1, p_feat1h, p_el1, p_er1, al1, ar1, NN, 512, 8);
    gemm_h<<<dim3(RB, 8), 256>>>(p_h, resW1, p_res1h, nullptr, nullptr, nullptr, nullptr, NN, 512, 8);
    agg1_kernel<<<NN, 256>>>(b1);
    pool_kernel<<<PB, 64>>>(p_h2, p_p1, gid);
    // layer-2: feature GEMM with fused el/er (1 head)
    gemm_h<<<dim3(RB, 1), 256>>>(p_h2, fcW2, p_feat2h, p_el2, p_er2, al2, ar2, NN, 64, 1);
    agg2_kernel<<<NN, 64>>>(b2);
    pool_kernel<<<PB, 64>>>(p_h3, p_p2, gid);
    // readout + MLP head
    hg_kernel<<<GG, 64>>>(gW1, gb1, gW2, gb2);
    fc_small<<<GG, 256>>>(p_hg, mW0, mb0, p_t0, 64, 256, 1);
    fc_small<<<GG, 256>>>(p_t0, mW1, mb1, p_t1, 256, 256, 1);
    fc_small<<<GG, 256>>>(p_t1, mW2, mb2, out, 256, 256, 0);
}

// round 5
// speedup vs baseline: 1.5081x; 1.2975x over previous
#include <cuda_runtime.h>
#include <cuda_fp16.h>
#include <mma.h>
#include <math.h>

using namespace nvcuda;

#define NN 30000
#define EE 480000
#define GG 64
#define HFD 64
#define NHEADS 8
#define MLPD 256

// ---------------- scratch (static device memory) ----------------
__device__ float  g_h[NN * HFD];
__device__ __half g_feat1h[NN * NHEADS * HFD];
__device__ __half g_res1h[NN * NHEADS * HFD];
__device__ float  g_el1[NN * NHEADS];
__device__ float  g_er1[NN * NHEADS];
__device__ int    g_cnt[NN];
__device__ int    g_indptr[NN + 1];
__device__ int    g_csr_src[EE];
__device__ float  g_h2[NN * HFD];
__device__ __half g_feat2h[NN * HFD];
__device__ float  g_el2[NN];
__device__ float  g_er2[NN];
__device__ float  g_h3[NN * HFD];
__device__ float  g_p0[GG * HFD];
__device__ float  g_p1[GG * HFD];
__device__ float  g_p2[GG * HFD];
__device__ float  g_hg[GG * HFD];
__device__ float  g_t0[GG * MLPD];
__device__ float  g_t1[GG * MLPD];

// ---------------- f32x2 helpers (projection GEMM stays fp32) ----------------
__device__ __forceinline__ void fma2(unsigned long long& d, unsigned long long a,
                                     unsigned long long b) {
    asm("fma.rn.f32x2 %0, %1, %2, %0;" : "+l"(d) : "l"(a), "l"(b));
}
__device__ __forceinline__ float2 unpk(unsigned long long v) {
    float2 r;
    asm("mov.b64 {%0,%1}, %2;" : "=f"(r.x), "=f"(r.y) : "l"(v));
    return r;
}

// ---------------- init ----------------
__global__ void zero_kernel() {
    int i = blockIdx.x * blockDim.x + threadIdx.x;
    if (i < NN) g_cnt[i] = 0;
    if (i < GG * HFD) { g_p0[i] = 0.f; g_p1[i] = 0.f; g_p2[i] = 0.f; }
}

// ---------------- fp32 projection GEMM (f32x2), 128x64 tile ----------------
__global__ __launch_bounds__(256, 2)
void gemm_t(const float* __restrict__ A, const float* __restrict__ W,
            const float* __restrict__ bias, float* __restrict__ Out,
            int nrows, int ncols) {
    __shared__ float sA[128 * 32];
    __shared__ float sW[64 * 34];
    int r0 = blockIdx.x * 128, c0 = blockIdx.y * 64;
    int tid = threadIdx.x;
    int rt = (tid >> 4) << 3, ct = tid & 15;
    unsigned long long acc[8][4];
#pragma unroll
    for (int i = 0; i < 8; i++)
#pragma unroll
        for (int j = 0; j < 4; j++) acc[i][j] = 0ULL;
    for (int kc = 0; kc < 64; kc += 32) {
#pragma unroll
        for (int i = 0; i < 4; i++) {
            int idx = tid + i * 256;
            int r = idx >> 3, k4 = (idx & 7) << 2;
            float4 v = make_float4(0.f, 0.f, 0.f, 0.f);
            if (r0 + r < nrows) v = *(const float4*)(A + (size_t)(r0 + r) * 64 + kc + k4);
            *(float4*)(sA + r * 32 + k4) = v;
        }
#pragma unroll
        for (int i = 0; i < 2; i++) {
            int idx = tid + i * 256;
            int kw = idx >> 4, cw = (idx & 15) << 2;
            float4 v = *(const float4*)(W + (size_t)(kc + kw) * ncols + c0 + cw);
            sW[(cw + 0) * 34 + kw] = v.x;
            sW[(cw + 1) * 34 + kw] = v.y;
            sW[(cw + 2) * 34 + kw] = v.z;
            sW[(cw + 3) * 34 + kw] = v.w;
        }
        __syncthreads();
#pragma unroll 4
        for (int kp = 0; kp < 16; kp++) {
            unsigned long long w0 = *(const unsigned long long*)(sW + (ct +  0) * 34 + 2 * kp);
            unsigned long long w1 = *(const unsigned long long*)(sW + (ct + 16) * 34 + 2 * kp);
            unsigned long long w2 = *(const unsigned long long*)(sW + (ct + 32) * 34 + 2 * kp);
            unsigned long long w3 = *(const unsigned long long*)(sW + (ct + 48) * 34 + 2 * kp);
#pragma unroll
            for (int i = 0; i < 8; i++) {
                unsigned long long av = *(const unsigned long long*)(sA + (rt + i) * 32 + 2 * kp);
                fma2(acc[i][0], av, w0);
                fma2(acc[i][1], av, w1);
                fma2(acc[i][2], av, w2);
                fma2(acc[i][3], av, w3);
            }
        }
        __syncthreads();
    }
#pragma unroll
    for (int j = 0; j < 4; j++) {
        int c = c0 + ct + 16 * j;
        float bv = bias ? bias[c] : 0.f;
#pragma unroll
        for (int i = 0; i < 8; i++) {
            int r = r0 + rt + i;
            if (r < nrows) {
                float2 u = unpk(acc[i][j]);
                Out[(size_t)r * ncols + c] = u.x + u.y + bv;
            }
        }
    }
}

// ---------------- tensor-core GEMM (fp16 in/out, fp32 acc) + fused attn dots ----
// Tile 128 rows x 64 cols, K=64. 8 warps: warp w -> rows 16w..16w+15.
// smem: phase 1 sA(128x72 half) + sW(64x72 half); phase 2 sC(128x68 float) aliased.
__global__ __launch_bounds__(256, 2)
void gemm_mma(const float* __restrict__ A, const float* __restrict__ W,
              __half* __restrict__ OutH,
              float* __restrict__ el, float* __restrict__ er,
              const float* __restrict__ al, const float* __restrict__ ar,
              int nrows, int ncols, int hstride) {
    __shared__ __align__(16) unsigned char smem_raw[128 * 68 * 4];  // 34816 B
    __half* sA = (__half*)smem_raw;                    // 128*72 halfs = 18432 B
    __half* sW = (__half*)(smem_raw + 128 * 72 * 2);   // 64*72 halfs = 9216 B
    float*  sC = (float*)smem_raw;                     // 128*68 floats = 34816 B

    int r0 = blockIdx.x * 128, c0 = blockIdx.y * 64;
    int tid = threadIdx.x;
    int w = tid >> 5;

    // load + convert A tile (128x64 fp32 -> fp16, ld 72)
#pragma unroll
    for (int i = 0; i < 8; i++) {
        int idx = tid + i * 256;           // 2048 float4 slots
        int r = idx >> 4, k4 = (idx & 15) << 2;
        float4 v = make_float4(0.f, 0.f, 0.f, 0.f);
        if (r0 + r < nrows) v = *(const float4*)(A + (size_t)(r0 + r) * 64 + k4);
        *(__half2*)(sA + r * 72 + k4)     = __floats2half2_rn(v.x, v.y);
        *(__half2*)(sA + r * 72 + k4 + 2) = __floats2half2_rn(v.z, v.w);
    }
    // load + convert W tile (64x64 -> ld 72)
#pragma unroll
    for (int i = 0; i < 4; i++) {
        int idx = tid + i * 256;           // 1024 float4 slots
        int kw = idx >> 4, cw = (idx & 15) << 2;
        float4 v = *(const float4*)(W + (size_t)kw * ncols + c0 + cw);
        *(__half2*)(sW + kw * 72 + cw)     = __floats2half2_rn(v.x, v.y);
        *(__half2*)(sW + kw * 72 + cw + 2) = __floats2half2_rn(v.z, v.w);
    }
    __syncthreads();

    wmma::fragment<wmma::matrix_a, 16, 16, 16, __half, wmma::row_major> fa;
    wmma::fragment<wmma::matrix_b, 16, 16, 16, __half, wmma::row_major> fb;
    wmma::fragment<wmma::accumulator, 16, 16, 16, float> fc[4];
#pragma unroll
    for (int n = 0; n < 4; n++) wmma::fill_fragment(fc[n], 0.f);
#pragma unroll
    for (int k0 = 0; k0 < 4; k0++) {
        wmma::load_matrix_sync(fa, sA + w * 16 * 72 + k0 * 16, 72);
#pragma unroll
        for (int n = 0; n < 4; n++) {
            wmma::load_matrix_sync(fb, sW + k0 * 16 * 72 + n * 16, 72);
            wmma::mma_sync(fc[n], fa, fb, fc[n]);
        }
    }
    __syncthreads();  // all warps done reading sA/sW before aliasing as sC
#pragma unroll
    for (int n = 0; n < 4; n++)
        wmma::store_matrix_sync(sC + w * 16 * 68 + n * 16, fc[n], 68, wmma::mem_row_major);
    __syncthreads();

    // epilogue: 2 threads per row; fp16 store + el/er dot
    int r = tid >> 1, part = tid & 1;
    int cb = part * 32;
    int grow = r0 + r;
    bool valid = grow < nrows;
    float elp = 0.f, erp = 0.f;
#pragma unroll
    for (int i = 0; i < 32; i += 2) {
        float v0 = sC[r * 68 + cb + i];
        float v1 = sC[r * 68 + cb + i + 1];
        if (valid)
            *(__half2*)(OutH + (size_t)grow * ncols + c0 + cb + i) = __floats2half2_rn(v0, v1);
        if (al) {
            elp += v0 * al[c0 + cb + i] + v1 * al[c0 + cb + i + 1];
            erp += v0 * ar[c0 + cb + i] + v1 * ar[c0 + cb + i + 1];
        }
    }
    if (al) {
        elp += __shfl_xor_sync(0xffffffffu, elp, 1);
        erp += __shfl_xor_sync(0xffffffffu, erp, 1);
        if (part == 0 && valid) {
            int head = c0 >> 6;
            el[(size_t)grow * hstride + head] = elp;
            er[(size_t)grow * hstride + head] = erp;
        }
    }
}

// ---------------- segment-sum pool by (sorted) graph_id ----------------
__global__ void pool_kernel(const float* __restrict__ x, float* __restrict__ out,
                            const int* __restrict__ gid) {
    int n0 = blockIdx.x * 256;
    int n1 = min(n0 + 256, NN);
    if (n0 >= NN) return;
    int c = threadIdx.x;  // 64
    int cur = gid[n0];
    float s = 0.f;
    for (int n = n0; n < n1; n++) {
        int g = gid[n];
        if (g != cur) { atomicAdd(&out[cur * HFD + c], s); s = 0.f; cur = g; }
        s += x[(size_t)n * HFD + c];
    }
    atomicAdd(&out[cur * HFD + c], s);
}

__device__ __forceinline__ float leaky02(float v) { return v > 0.f ? v : 0.2f * v; }

// ---------------- CSR build ----------------
__global__ void count_kernel(const int* __restrict__ dst) {
    int e = blockIdx.x * 256 + threadIdx.x;
    if (e < EE) atomicAdd(&g_cnt[dst[e]], 1);
}

__global__ void scan_kernel() {
    __shared__ int sh[1024];
    int tid = threadIdx.x;
    const int CH = (NN + 1023) / 1024;
    int lo = tid * CH, hi = min(lo + CH, NN);
    int s = 0;
    for (int i = lo; i < hi; i++) s += g_cnt[i];
    sh[tid] = s;
    __syncthreads();
    for (int off = 1; off < 1024; off <<= 1) {
        int v = (tid >= off) ? sh[tid - off] : 0;
        __syncthreads();
        sh[tid] += v;
        __syncthreads();
    }
    int run = sh[tid] - s;
    for (int i = lo; i < hi; i++) { g_indptr[i] = run; run += g_cnt[i]; g_cnt[i] = 0; }
    if (tid == 1023) g_indptr[NN] = sh[1023];
}

__global__ void scatter_kernel(const int* __restrict__ src, const int* __restrict__ dst) {
    int e = blockIdx.x * 256 + threadIdx.x;
    if (e >= EE) return;
    int d = dst[e];
    int pos = g_indptr[d] + atomicAdd(&g_cnt[d], 1);
    g_csr_src[pos] = src[e];
}

// ---------------- layer-1: softmax-agg + residual + bias + ELU + LN + head-mean ----
__global__ void agg1_kernel(const float* __restrict__ b1) {
    int n = blockIdx.x;
    int tid = threadIdx.x;  // 256
    int h = tid >> 5, lane = tid & 31;
    __shared__ float s_w[32][8];
    __shared__ int s_src[32];
    __shared__ float s_er[8];
    __shared__ float s_out[8][64];
    int base = g_indptr[n];
    int deg = g_indptr[n + 1] - base;
    if (tid < 8) s_er[tid] = g_er1[n * 8 + tid];

    float acc0 = 0.f, acc1 = 0.f, wsum = 0.f;
    int c0 = lane * 2;
    for (int cs = 0; cs < deg; cs += 32) {
        int nc = min(32, deg - cs);
        __syncthreads();
        if (tid < nc * 8) {
            int j = tid >> 3, hh = tid & 7;
            int s = g_csr_src[base + cs + j];
            if ((tid & 7) == 0) s_src[j] = s;
            s_w[j][hh] = __expf(leaky02(g_el1[s * 8 + hh] + s_er[hh]));
        }
        __syncthreads();
#pragma unroll 4
        for (int j = 0; j < nc; j++) {
            int s = s_src[j];
            __half2 hf = *(const __half2*)(g_feat1h + (size_t)s * 512 + h * 64 + c0);
            float2 f = __half22float2(hf);
            float w = s_w[j][h];
            acc0 += w * f.x;
            acc1 += w * f.y;
            wsum += w;
        }
    }
    float inv = wsum > 0.f ? 1.f / wsum : 0.f;
    float2 rr = __half22float2(*(const __half2*)(g_res1h + (size_t)n * 512 + h * 64 + c0));
    float2 bb = *(const float2*)(b1 + h * 64 + c0);
    float v0 = acc0 * inv + rr.x + bb.x;
    float v1 = acc1 * inv + rr.y + bb.y;
    v0 = v0 > 0.f ? v0 : (__expf(v0) - 1.f);
    v1 = v1 > 0.f ? v1 : (__expf(v1) - 1.f);
    float s = v0 + v1, ss = v0 * v0 + v1 * v1;
#pragma unroll
    for (int o = 16; o; o >>= 1) {
        s += __shfl_xor_sync(0xffffffffu, s, o);
        ss += __shfl_xor_sync(0xffffffffu, ss, o);
    }
    float mu = s * (1.f / 64.f);
    float var = ss * (1.f / 64.f) - mu * mu;
    float rs = rsqrtf(var + 1e-5f);
    s_out[h][c0] = (v0 - mu) * rs;
    s_out[h][c0 + 1] = (v1 - mu) * rs;
    __syncthreads();
    if (tid < 64) {
        float t = 0.f;
#pragma unroll
        for (int hh = 0; hh < 8; hh++) t += s_out[hh][tid];
        g_h2[(size_t)n * 64 + tid] = t * 0.125f;
    }
}

// ---------------- layer-2: softmax-agg + identity residual + bias + ELU + LN ----
__global__ void agg2_kernel(const float* __restrict__ b2) {
    int n = blockIdx.x;
    int tid = threadIdx.x;  // 64
    __shared__ float s_w[64];
    __shared__ int s_src[64];
    __shared__ float s_red[2], s_red2[2];
    int base = g_indptr[n];
    int deg = g_indptr[n + 1] - base;
    float er = g_er2[n];
    float acc = 0.f, wsum = 0.f;
    for (int cs = 0; cs < deg; cs += 64) {
        int nc = min(64, deg - cs);
        __syncthreads();
        if (tid < nc) {
            int s = g_csr_src[base + cs + tid];
            s_src[tid] = s;
            s_w[tid] = __expf(leaky02(g_el2[s] + er));
        }
        __syncthreads();
#pragma unroll 4
        for (int j = 0; j < nc; j++) {
            float w = s_w[j];
            acc += w * __half2float(g_feat2h[(size_t)s_src[j] * 64 + tid]);
            wsum += w;
        }
    }
    float inv = wsum > 0.f ? 1.f / wsum : 0.f;
    float v = acc * inv + g_h2[(size_t)n * 64 + tid] + b2[tid];
    v = v > 0.f ? v : (__expf(v) - 1.f);
    float s = v, ss = v * v;
#pragma unroll
    for (int o = 16; o; o >>= 1) {
        s += __shfl_xor_sync(0xffffffffu, s, o);
        ss += __shfl_xor_sync(0xffffffffu, ss, o);
    }
    __syncthreads();
    if ((tid & 31) == 0) { s_red[tid >> 5] = s; s_red2[tid >> 5] = ss; }
    __syncthreads();
    s = s_red[0] + s_red[1];
    ss = s_red2[0] + s_red2[1];
    float mu = s * (1.f / 64.f);
    float var = ss * (1.f / 64.f) - mu * mu;
    g_h3[(size_t)n * 64 + tid] = (v - mu) * rsqrtf(var + 1e-5f);
}

// ---------------- graph-level readout ----------------
__global__ void hg_kernel(const float* __restrict__ gW1, const float* __restrict__ gb1,
                          const float* __restrict__ gW2, const float* __restrict__ gb2) {
    int g = blockIdx.x, c = threadIdx.x;  // 64
    float a = gb1[c], b = gb2[c];
    for (int k = 0; k < 64; k++) {
        a += g_p1[g * 64 + k] * gW1[k * 64 + c];
        b += g_p2[g * 64 + k] * gW2[k * 64 + c];
    }
    a = a > 0.f ? a : 0.01f * a;
    b = b > 0.f ? b : 0.01f * b;
    g_hg[g * 64 + c] = g_p0[g * 64 + c] + a + b;
}

// ---------------- small FC ----------------
__global__ void fc_small(const float* __restrict__ in, const float* __restrict__ W,
                         const float* __restrict__ b, float* __restrict__ out,
                         int K, int C, int do_relu) {
    int g = blockIdx.x, c = threadIdx.x;
    float a = b[c];
    for (int k = 0; k < K; k++) a += in[g * K + k] * W[k * C + c];
    if (do_relu) a = fmaxf(a, 0.f);
    out[g * C + c] = a;
}

// ---------------- launch ----------------
extern "C" void kernel_launch(void* const* d_in, const int* in_sizes, int n_in,
                              void* d_out, int out_size) {
    const float* X     = (const float*)d_in[0];
    const int*   src   = (const int*)d_in[1];
    const int*   dst   = (const int*)d_in[2];
    const int*   gid   = (const int*)d_in[3];
    const float* projW = (const float*)d_in[4];
    const float* projb = (const float*)d_in[5];
    const float* fcW1  = (const float*)d_in[6];
    const float* al1   = (const float*)d_in[7];
    const float* ar1   = (const float*)d_in[8];
    const float* resW1 = (const float*)d_in[9];
    const float* b1    = (const float*)d_in[10];
    const float* fcW2  = (const float*)d_in[11];
    const float* al2   = (const float*)d_in[12];
    const float* ar2   = (const float*)d_in[13];
    const float* b2    = (const float*)d_in[14];
    const float* gW1   = (const float*)d_in[15];
    const float* gb1   = (const float*)d_in[16];
    const float* gW2   = (const float*)d_in[17];
    const float* gb2   = (const float*)d_in[18];
    const float* mW0   = (const float*)d_in[19];
    const float* mb0   = (const float*)d_in[20];
    const float* mW1   = (const float*)d_in[21];
    const float* mb1   = (const float*)d_in[22];
    const float* mW2   = (const float*)d_in[23];
    const float* mb2   = (const float*)d_in[24];
    float* out = (float*)d_out;

    float *p_h, *p_h2, *p_h3, *p_p0, *p_p1, *p_p2, *p_hg, *p_t0, *p_t1;
    float *p_el1, *p_er1, *p_el2, *p_er2;
    __half *p_feat1h, *p_res1h, *p_feat2h;
    cudaGetSymbolAddress((void**)&p_h, g_h);
    cudaGetSymbolAddress((void**)&p_feat1h, g_feat1h);
    cudaGetSymbolAddress((void**)&p_res1h, g_res1h);
    cudaGetSymbolAddress((void**)&p_el1, g_el1);
    cudaGetSymbolAddress((void**)&p_er1, g_er1);
    cudaGetSymbolAddress((void**)&p_h2, g_h2);
    cudaGetSymbolAddress((void**)&p_feat2h, g_feat2h);
    cudaGetSymbolAddress((void**)&p_el2, g_el2);
    cudaGetSymbolAddress((void**)&p_er2, g_er2);
    cudaGetSymbolAddress((void**)&p_h3, g_h3);
    cudaGetSymbolAddress((void**)&p_p0, g_p0);
    cudaGetSymbolAddress((void**)&p_p1, g_p1);
    cudaGetSymbolAddress((void**)&p_p2, g_p2);
    cudaGetSymbolAddress((void**)&p_hg, g_hg);
    cudaGetSymbolAddress((void**)&p_t0, g_t0);
    cudaGetSymbolAddress((void**)&p_t1, g_t1);

    // one-time host resources (no device memory involved)
    static cudaStream_t s1 = nullptr;
    static cudaEvent_t evStart, evProj, evCSR, evH2, evPools;
    if (!s1) {
        cudaStreamCreateWithFlags(&s1, cudaStreamNonBlocking);
        cudaEventCreateWithFlags(&evStart, cudaEventDisableTiming);
        cudaEventCreateWithFlags(&evProj, cudaEventDisableTiming);
        cudaEventCreateWithFlags(&evCSR, cudaEventDisableTiming);
        cudaEventCreateWithFlags(&evH2, cudaEventDisableTiming);
        cudaEventCreateWithFlags(&evPools, cudaEventDisableTiming);
    }

    const int EB = (EE + 255) / 256;
    const int RB = (NN + 127) / 128;   // 235
    const int PB = (NN + 255) / 256;

    // fork: side stream does CSR build + pools
    cudaEventRecord(evStart, 0);
    cudaStreamWaitEvent(s1, evStart, 0);
    zero_kernel<<<(NN + 255) / 256, 256, 0, s1>>>();
    count_kernel<<<EB, 256, 0, s1>>>(dst);
    scan_kernel<<<1, 1024, 0, s1>>>();
    scatter_kernel<<<EB, 256, 0, s1>>>(src, dst);
    cudaEventRecord(evCSR, s1);

    // main stream: projection + feature GEMMs (independent of CSR)
    gemm_t<<<dim3(RB, 1), 256>>>(X, projW, projb, p_h, NN, 64);
    cudaEventRecord(evProj, 0);
    cudaStreamWaitEvent(s1, evProj, 0);
    pool_kernel<<<PB, 64, 0, s1>>>(p_h, p_p0, gid);   // after zero + proj

    gemm_mma<<<dim3(RB, 8), 256>>>(p_h, fcW1, p_feat1h, p_el1, p_er1, al1, ar1, NN, 512, 8);
    gemm_mma<<<dim3(RB, 8), 256>>>(p_h, resW1, p_res1h, nullptr, nullptr, nullptr, nullptr, NN, 512, 8);

    cudaStreamWaitEvent(0, evCSR, 0);
    agg1_kernel<<<NN, 256>>>(b1);
    cudaEventRecord(evH2, 0);
    cudaStreamWaitEvent(s1, evH2, 0);
    pool_kernel<<<PB, 64, 0, s1>>>(p_h2, p_p1, gid);
    cudaEventRecord(evPools, s1);

    gemm_mma<<<dim3(RB, 1), 256>>>(p_h2, fcW2, p_feat2h, p_el2, p_er2, al2, ar2, NN, 64, 1);
    agg2_kernel<<<NN, 64>>>(b2);
    pool_kernel<<<PB, 64>>>(p_h3, p_p2, gid);

    // join + readout + MLP head
    cudaStreamWaitEvent(0, evPools, 0);
    hg_kernel<<<GG, 64>>>(gW1, gb1, gW2, gb2);
    fc_small<<<GG, 256>>>(p_hg, mW0, mb0, p_t0, 64, 256, 1);
    fc_small<<<GG, 256>>>(p_t0, mW1, mb1, p_t1, 256, 256, 1);
    fc_small<<<GG, 256>>>(p_t1, mW2, mb2, out, 256, 256, 0);
}

// round 7
// speedup vs baseline: 1.6964x; 1.1249x over previous
#include <cuda_runtime.h>
#include <cuda_fp16.h>
#include <mma.h>
#include <math.h>

using namespace nvcuda;

#define NN 30000
#define EE 480000
#define GG 64
#define HFD 64
#define NHEADS 8
#define MLPD 256

// ---------------- scratch (static device memory) ----------------
__device__ float  g_h[NN * HFD];
__device__ __half g_feat1h[NN * NHEADS * HFD];
__device__ __half g_res1h[NN * NHEADS * HFD];
__device__ float  g_el1[NN * NHEADS];
__device__ float  g_er1[NN * NHEADS];
__device__ int    g_cnt[NN];
__device__ int    g_indptr[NN + 1];
__device__ int    g_csr_src[EE];
__device__ float  g_h2[NN * HFD];
__device__ __half g_feat2h[NN * HFD];
__device__ float  g_el2[NN];
__device__ float  g_er2[NN];
__device__ float  g_h3[NN * HFD];
__device__ float  g_p0[GG * HFD];
__device__ float  g_p1[GG * HFD];
__device__ float  g_p2[GG * HFD];
__device__ float  g_hg[GG * HFD];
__device__ float  g_t0[GG * MLPD];
__device__ float  g_t1[GG * MLPD];

// ---------------- f32x2 helpers ----------------
__device__ __forceinline__ void fma2(unsigned long long& d, unsigned long long a,
                                     unsigned long long b) {
    asm("fma.rn.f32x2 %0, %1, %2, %0;" : "+l"(d) : "l"(a), "l"(b));
}
__device__ __forceinline__ float2 unpk(unsigned long long v) {
    float2 r;
    asm("mov.b64 {%0,%1}, %2;" : "=f"(r.x), "=f"(r.y) : "l"(v));
    return r;
}

// ---------------- init ----------------
__global__ void zero_kernel() {
    int i = blockIdx.x * blockDim.x + threadIdx.x;
    if (i < NN) g_cnt[i] = 0;
    if (i < GG * HFD) { g_p0[i] = 0.f; g_p1[i] = 0.f; g_p2[i] = 0.f; }
}

// ---------------- fp32 projection GEMM (f32x2), 128x64 tile ----------------
__global__ __launch_bounds__(256, 2)
void gemm_t(const float* __restrict__ A, const float* __restrict__ W,
            const float* __restrict__ bias, float* __restrict__ Out,
            int nrows, int ncols) {
    __shared__ float sA[128 * 32];
    __shared__ float sW[64 * 34];
    int r0 = blockIdx.x * 128, c0 = blockIdx.y * 64;
    int tid = threadIdx.x;
    int rt = (tid >> 4) << 3, ct = tid & 15;
    unsigned long long acc[8][4];
#pragma unroll
    for (int i = 0; i < 8; i++)
#pragma unroll
        for (int j = 0; j < 4; j++) acc[i][j] = 0ULL;
    for (int kc = 0; kc < 64; kc += 32) {
#pragma unroll
        for (int i = 0; i < 4; i++) {
            int idx = tid + i * 256;
            int r = idx >> 3, k4 = (idx & 7) << 2;
            float4 v = make_float4(0.f, 0.f, 0.f, 0.f);
            if (r0 + r < nrows) v = *(const float4*)(A + (size_t)(r0 + r) * 64 + kc + k4);
            *(float4*)(sA + r * 32 + k4) = v;
        }
#pragma unroll
        for (int i = 0; i < 2; i++) {
            int idx = tid + i * 256;
            int kw = idx >> 4, cw = (idx & 15) << 2;
            float4 v = *(const float4*)(W + (size_t)(kc + kw) * ncols + c0 + cw);
            sW[(cw + 0) * 34 + kw] = v.x;
            sW[(cw + 1) * 34 + kw] = v.y;
            sW[(cw + 2) * 34 + kw] = v.z;
            sW[(cw + 3) * 34 + kw] = v.w;
        }
        __syncthreads();
#pragma unroll 4
        for (int kp = 0; kp < 16; kp++) {
            unsigned long long w0 = *(const unsigned long long*)(sW + (ct +  0) * 34 + 2 * kp);
            unsigned long long w1 = *(const unsigned long long*)(sW + (ct + 16) * 34 + 2 * kp);
            unsigned long long w2 = *(const unsigned long long*)(sW + (ct + 32) * 34 + 2 * kp);
            unsigned long long w3 = *(const unsigned long long*)(sW + (ct + 48) * 34 + 2 * kp);
#pragma unroll
            for (int i = 0; i < 8; i++) {
                unsigned long long av = *(const unsigned long long*)(sA + (rt + i) * 32 + 2 * kp);
                fma2(acc[i][0], av, w0);
                fma2(acc[i][1], av, w1);
                fma2(acc[i][2], av, w2);
                fma2(acc[i][3], av, w3);
            }
        }
        __syncthreads();
    }
#pragma unroll
    for (int j = 0; j < 4; j++) {
        int c = c0 + ct + 16 * j;
        float bv = bias ? bias[c] : 0.f;
#pragma unroll
        for (int i = 0; i < 8; i++) {
            int r = r0 + rt + i;
            if (r < nrows) {
                float2 u = unpk(acc[i][j]);
                Out[(size_t)r * ncols + c] = u.x + u.y + bv;
            }
        }
    }
}

// ---------------- tensor-core GEMM (fp16 in/out, fp32 acc) + fused attn dots ----
__global__ __launch_bounds__(256, 2)
void gemm_mma(const float* __restrict__ A, const float* __restrict__ W,
              __half* __restrict__ OutH,
              float* __restrict__ el, float* __restrict__ er,
              const float* __restrict__ al, const float* __restrict__ ar,
              int nrows, int ncols, int hstride) {
    __shared__ __align__(16) unsigned char smem_raw[128 * 68 * 4];
    __half* sA = (__half*)smem_raw;
    __half* sW = (__half*)(smem_raw + 128 * 72 * 2);
    float*  sC = (float*)smem_raw;

    int r0 = blockIdx.x * 128, c0 = blockIdx.y * 64;
    int tid = threadIdx.x;
    int w = tid >> 5;

#pragma unroll
    for (int i = 0; i < 8; i++) {
        int idx = tid + i * 256;
        int r = idx >> 4, k4 = (idx & 15) << 2;
        float4 v = make_float4(0.f, 0.f, 0.f, 0.f);
        if (r0 + r < nrows) v = *(const float4*)(A + (size_t)(r0 + r) * 64 + k4);
        *(__half2*)(sA + r * 72 + k4)     = __floats2half2_rn(v.x, v.y);
        *(__half2*)(sA + r * 72 + k4 + 2) = __floats2half2_rn(v.z, v.w);
    }
#pragma unroll
    for (int i = 0; i < 4; i++) {
        int idx = tid + i * 256;
        int kw = idx >> 4, cw = (idx & 15) << 2;
        float4 v = *(const float4*)(W + (size_t)kw * ncols + c0 + cw);
        *(__half2*)(sW + kw * 72 + cw)     = __floats2half2_rn(v.x, v.y);
        *(__half2*)(sW + kw * 72 + cw + 2) = __floats2half2_rn(v.z, v.w);
    }
    __syncthreads();

    wmma::fragment<wmma::matrix_a, 16, 16, 16, __half, wmma::row_major> fa;
    wmma::fragment<wmma::matrix_b, 16, 16, 16, __half, wmma::row_major> fb;
    wmma::fragment<wmma::accumulator, 16, 16, 16, float> fc[4];
#pragma unroll
    for (int n = 0; n < 4; n++) wmma::fill_fragment(fc[n], 0.f);
#pragma unroll
    for (int k0 = 0; k0 < 4; k0++) {
        wmma::load_matrix_sync(fa, sA + w * 16 * 72 + k0 * 16, 72);
#pragma unroll
        for (int n = 0; n < 4; n++) {
            wmma::load_matrix_sync(fb, sW + k0 * 16 * 72 + n * 16, 72);
            wmma::mma_sync(fc[n], fa, fb, fc[n]);
        }
    }
    __syncthreads();
#pragma unroll
    for (int n = 0; n < 4; n++)
        wmma::store_matrix_sync(sC + w * 16 * 68 + n * 16, fc[n], 68, wmma::mem_row_major);
    __syncthreads();

    int r = tid >> 1, part = tid & 1;
    int cb = part * 32;
    int grow = r0 + r;
    bool valid = grow < nrows;
    float elp = 0.f, erp = 0.f;
#pragma unroll
    for (int i = 0; i < 32; i += 2) {
        float v0 = sC[r * 68 + cb + i];
        float v1 = sC[r * 68 + cb + i + 1];
        if (valid)
            *(__half2*)(OutH + (size_t)grow * ncols + c0 + cb + i) = __floats2half2_rn(v0, v1);
        if (al) {
            elp += v0 * al[c0 + cb + i] + v1 * al[c0 + cb + i + 1];
            erp += v0 * ar[c0 + cb + i] + v1 * ar[c0 + cb + i + 1];
        }
    }
    if (al) {
        elp += __shfl_xor_sync(0xffffffffu, elp, 1);
        erp += __shfl_xor_sync(0xffffffffu, erp, 1);
        if (part == 0 && valid) {
            int head = c0 >> 6;
            el[(size_t)grow * hstride + head] = elp;
            er[(size_t)grow * hstride + head] = erp;
        }
    }
}

// ---------------- segment-sum pool: 32 rows per block ----------------
__global__ void pool_kernel(const float* __restrict__ x, float* __restrict__ out,
                            const int* __restrict__ gid) {
    int n0 = blockIdx.x * 32;
    int n1 = min(n0 + 32, NN);
    if (n0 >= NN) return;
    int c = threadIdx.x;  // 64
    int cur = gid[n0];
    float s = 0.f;
    for (int n = n0; n < n1; n++) {
        int g = gid[n];
        if (g != cur) { atomicAdd(&out[cur * HFD + c], s); s = 0.f; cur = g; }
        s += x[(size_t)n * HFD + c];
    }
    atomicAdd(&out[cur * HFD + c], s);
}

__device__ __forceinline__ float leaky02(float v) { return v > 0.f ? v : 0.2f * v; }

// ---------------- CSR build ----------------
__global__ void count_kernel(const int* __restrict__ dst) {
    int e = blockIdx.x * 256 + threadIdx.x;
    if (e < EE) atomicAdd(&g_cnt[dst[e]], 1);
}

__global__ void scan_kernel() {
    __shared__ int sh[1024];
    int tid = threadIdx.x;
    const int CH = (NN + 1023) / 1024;
    int lo = tid * CH, hi = min(lo + CH, NN);
    int s = 0;
    for (int i = lo; i < hi; i++) s += g_cnt[i];
    sh[tid] = s;
    __syncthreads();
    for (int off = 1; off < 1024; off <<= 1) {
        int v = (tid >= off) ? sh[tid - off] : 0;
        __syncthreads();
        sh[tid] += v;
        __syncthreads();
    }
    int run = sh[tid] - s;
    for (int i = lo; i < hi; i++) { g_indptr[i] = run; run += g_cnt[i]; g_cnt[i] = 0; }
    if (tid == 1023) g_indptr[NN] = sh[1023];
}

__global__ void scatter_kernel(const int* __restrict__ src, const int* __restrict__ dst) {
    int e = blockIdx.x * 256 + threadIdx.x;
    if (e >= EE) return;
    int d = dst[e];
    int pos = g_indptr[d] + atomicAdd(&g_cnt[d], 1);
    g_csr_src[pos] = src[e];
}

// ---------------- layer-1: softmax-agg + residual + bias + ELU + LN + head-mean ----
__global__ void agg1_kernel(const float* __restrict__ b1) {
    int n = blockIdx.x;
    int tid = threadIdx.x;  // 256
    int h = tid >> 5, lane = tid & 31;
    __shared__ float s_w[32][8];
    __shared__ int s_src[32];
    __shared__ float s_er[8];
    __shared__ float s_out[8][64];
    int base = g_indptr[n];
    int deg = g_indptr[n + 1] - base;
    if (tid < 8) s_er[tid] = g_er1[n * 8 + tid];

    float acc0 = 0.f, acc1 = 0.f, wsum = 0.f;
    int c0 = lane * 2;
    for (int cs = 0; cs < deg; cs += 32) {
        int nc = min(32, deg - cs);
        __syncthreads();
        if (tid < nc * 8) {
            int j = tid >> 3, hh = tid & 7;
            int s = g_csr_src[base + cs + j];
            if ((tid & 7) == 0) s_src[j] = s;
            s_w[j][hh] = __expf(leaky02(g_el1[s * 8 + hh] + s_er[hh]));
        }
        __syncthreads();
#pragma unroll 8
        for (int j = 0; j < nc; j++) {
            int s = s_src[j];
            __half2 hf = *(const __half2*)(g_feat1h + (size_t)s * 512 + h * 64 + c0);
            float2 f = __half22float2(hf);
            float w = s_w[j][h];
            acc0 += w * f.x;
            acc1 += w * f.y;
            wsum += w;
        }
    }
    float inv = wsum > 0.f ? 1.f / wsum : 0.f;
    float2 rr = __half22float2(*(const __half2*)(g_res1h + (size_t)n * 512 + h * 64 + c0));
    float2 bb = *(const float2*)(b1 + h * 64 + c0);
    float v0 = acc0 * inv + rr.x + bb.x;
    float v1 = acc1 * inv + rr.y + bb.y;
    v0 = v0 > 0.f ? v0 : (__expf(v0) - 1.f);
    v1 = v1 > 0.f ? v1 : (__expf(v1) - 1.f);
    float s = v0 + v1, ss = v0 * v0 + v1 * v1;
#pragma unroll
    for (int o = 16; o; o >>= 1) {
        s += __shfl_xor_sync(0xffffffffu, s, o);
        ss += __shfl_xor_sync(0xffffffffu, ss, o);
    }
    float mu = s * (1.f / 64.f);
    float var = ss * (1.f / 64.f) - mu * mu;
    float rs = rsqrtf(var + 1e-5f);
    s_out[h][c0] = (v0 - mu) * rs;
    s_out[h][c0 + 1] = (v1 - mu) * rs;
    __syncthreads();
    if (tid < 64) {
        float t = 0.f;
#pragma unroll
        for (int hh = 0; hh < 8; hh++) t += s_out[hh][tid];
        g_h2[(size_t)n * 64 + tid] = t * 0.125f;
    }
}

// ---------------- layer-2: softmax-agg + identity residual + bias + ELU + LN ----
__global__ void agg2_kernel(const float* __restrict__ b2) {
    int n = blockIdx.x;
    int tid = threadIdx.x;  // 64
    __shared__ float s_w[64];
    __shared__ int s_src[64];
    __shared__ float s_red[2], s_red2[2];
    int base = g_indptr[n];
    int deg = g_indptr[n + 1] - base;
    float er = g_er2[n];
    float acc = 0.f, wsum = 0.f;
    for (int cs = 0; cs < deg; cs += 64) {
        int nc = min(64, deg - cs);
        __syncthreads();
        if (tid < nc) {
            int s = g_csr_src[base + cs + tid];
            s_src[tid] = s;
            s_w[tid] = __expf(leaky02(g_el2[s] + er));
        }
        __syncthreads();
#pragma unroll 8
        for (int j = 0; j < nc; j++) {
            float w = s_w[j];
            acc += w * __half2float(g_feat2h[(size_t)s_src[j] * 64 + tid]);
            wsum += w;
        }
    }
    float inv = wsum > 0.f ? 1.f / wsum : 0.f;
    float v = acc * inv + g_h2[(size_t)n * 64 + tid] + b2[tid];
    v = v > 0.f ? v : (__expf(v) - 1.f);
    float s = v, ss = v * v;
#pragma unroll
    for (int o = 16; o; o >>= 1) {
        s += __shfl_xor_sync(0xffffffffu, s, o);
        ss += __shfl_xor_sync(0xffffffffu, ss, o);
    }
    __syncthreads();
    if ((tid & 31) == 0) { s_red[tid >> 5] = s; s_red2[tid >> 5] = ss; }
    __syncthreads();
    s = s_red[0] + s_red[1];
    ss = s_red2[0] + s_red2[1];
    float mu = s * (1.f / 64.f);
    float var = ss * (1.f / 64.f) - mu * mu;
    g_h3[(size_t)n * 64 + tid] = (v - mu) * rsqrtf(var + 1e-5f);
}

// ---------------- graph-level readout ----------------
__global__ void hg_kernel(const float* __restrict__ gW1, const float* __restrict__ gb1,
                          const float* __restrict__ gW2, const float* __restrict__ gb2) {
    int g = blockIdx.x, c = threadIdx.x;  // 64
    float a = gb1[c], b = gb2[c];
#pragma unroll 8
    for (int k = 0; k < 64; k++) {
        a += g_p1[g * 64 + k] * gW1[k * 64 + c];
        b += g_p2[g * 64 + k] * gW2[k * 64 + c];
    }
    a = a > 0.f ? a : 0.01f * a;
    b = b > 0.f ? b : 0.01f * b;
    g_hg[g * 64 + c] = g_p0[g * 64 + c] + a + b;
}

// ---------------- small FC (templated K, unrolled) ----------------
template <int K>
__global__ void fc_small(const float* __restrict__ in, const float* __restrict__ W,
                         const float* __restrict__ b, float* __restrict__ out,
                         int C, int do_relu) {
    int g = blockIdx.x, c = threadIdx.x;
    float a = b[c];
#pragma unroll 8
    for (int k = 0; k < K; k++) a += in[g * K + k] * W[k * C + c];
    if (do_relu) a = fmaxf(a, 0.f);
    out[g * C + c] = a;
}

// ---------------- launch ----------------
extern "C" void kernel_launch(void* const* d_in, const int* in_sizes, int n_in,
                              void* d_out, int out_size) {
    const float* X     = (const float*)d_in[0];
    const int*   src   = (const int*)d_in[1];
    const int*   dst   = (const int*)d_in[2];
    const int*   gid   = (const int*)d_in[3];
    const float* projW = (const float*)d_in[4];
    const float* projb = (const float*)d_in[5];
    const float* fcW1  = (const float*)d_in[6];
    const float* al1   = (const float*)d_in[7];
    const float* ar1   = (const float*)d_in[8];
    const float* resW1 = (const float*)d_in[9];
    const float* b1    = (const float*)d_in[10];
    const float* fcW2  = (const float*)d_in[11];
    const float* al2   = (const float*)d_in[12];
    const float* ar2   = (const float*)d_in[13];
    const float* b2    = (const float*)d_in[14];
    const float* gW1   = (const float*)d_in[15];
    const float* gb1   = (const float*)d_in[16];
    const float* gW2   = (const float*)d_in[17];
    const float* gb2   = (const float*)d_in[18];
    const float* mW0   = (const float*)d_in[19];
    const float* mb0   = (const float*)d_in[20];
    const float* mW1   = (const float*)d_in[21];
    const float* mb1   = (const float*)d_in[22];
    const float* mW2   = (const float*)d_in[23];
    const float* mb2   = (const float*)d_in[24];
    float* out = (float*)d_out;

    float *p_h, *p_h2, *p_h3, *p_p0, *p_p1, *p_p2, *p_hg, *p_t0, *p_t1;
    float *p_el1, *p_er1, *p_el2, *p_er2;
    __half *p_feat1h, *p_res1h, *p_feat2h;
    cudaGetSymbolAddress((void**)&p_h, g_h);
    cudaGetSymbolAddress((void**)&p_feat1h, g_feat1h);
    cudaGetSymbolAddress((void**)&p_res1h, g_res1h);
    cudaGetSymbolAddress((void**)&p_el1, g_el1);
    cudaGetSymbolAddress((void**)&p_er1, g_er1);
    cudaGetSymbolAddress((void**)&p_h2, g_h2);
    cudaGetSymbolAddress((void**)&p_feat2h, g_feat2h);
    cudaGetSymbolAddress((void**)&p_el2, g_el2);
    cudaGetSymbolAddress((void**)&p_er2, g_er2);
    cudaGetSymbolAddress((void**)&p_h3, g_h3);
    cudaGetSymbolAddress((void**)&p_p0, g_p0);
    cudaGetSymbolAddress((void**)&p_p1, g_p1);
    cudaGetSymbolAddress((void**)&p_p2, g_p2);
    cudaGetSymbolAddress((void**)&p_hg, g_hg);
    cudaGetSymbolAddress((void**)&p_t0, g_t0);
    cudaGetSymbolAddress((void**)&p_t1, g_t1);

    static cudaStream_t s1 = nullptr;
    static cudaEvent_t evStart, evProj, evCSR, evH2, evPools;
    if (!s1) {
        cudaStreamCreateWithFlags(&s1, cudaStreamNonBlocking);
        cudaEventCreateWithFlags(&evStart, cudaEventDisableTiming);
        cudaEventCreateWithFlags(&evProj, cudaEventDisableTiming);
        cudaEventCreateWithFlags(&evCSR, cudaEventDisableTiming);
        cudaEventCreateWithFlags(&evH2, cudaEventDisableTiming);
        cudaEventCreateWithFlags(&evPools, cudaEventDisableTiming);
    }

    const int EB = (EE + 255) / 256;
    const int RB = (NN + 127) / 128;   // 235
    const int PB = (NN + 31) / 32;     // 938

    // fork
    cudaEventRecord(evStart, 0);
    cudaStreamWaitEvent(s1, evStart, 0);

    // launch #1: zero (side stream)
    zero_kernel<<<(NN + 255) / 256, 256, 0, s1>>>();
    // launch #2: projection (main)
    gemm_t<<<dim3(RB, 1), 256>>>(X, projW, projb, p_h, NN, 64);
    cudaEventRecord(evProj, 0);
    // launch #3: residual GEMM (main)
    gemm_mma<<<dim3(RB, 8), 256>>>(p_h, resW1, p_res1h, nullptr, nullptr, nullptr, nullptr, NN, 512, 8);
    // launch #4 (PROFILED by ncu -s): feature GEMM with fused attn dots
    gemm_mma<<<dim3(RB, 8), 256>>>(p_h, fcW1, p_feat1h, p_el1, p_er1, al1, ar1, NN, 512, 8);

    // side stream: CSR build + pool0
    count_kernel<<<EB, 256, 0, s1>>>(dst);
    scan_kernel<<<1, 1024, 0, s1>>>();
    scatter_kernel<<<EB, 256, 0, s1>>>(src, dst);
    cudaEventRecord(evCSR, s1);
    cudaStreamWaitEvent(s1, evProj, 0);
    pool_kernel<<<PB, 64, 0, s1>>>(p_h, p_p0, gid);

    // main: aggregation layer 1 (needs CSR + both GEMMs)
    cudaStreamWaitEvent(0, evCSR, 0);
    agg1_kernel<<<NN, 256>>>(b1);
    cudaEventRecord(evH2, 0);
    cudaStreamWaitEvent(s1, evH2, 0);
    pool_kernel<<<PB, 64, 0, s1>>>(p_h2, p_p1, gid);
    cudaEventRecord(evPools, s1);

    // layer 2
    gemm_mma<<<dim3(RB, 1), 256>>>(p_h2, fcW2, p_feat2h, p_el2, p_er2, al2, ar2, NN, 64, 1);
    agg2_kernel<<<NN, 64>>>(b2);
    pool_kernel<<<PB, 64>>>(p_h3, p_p2, gid);

    // join + readout + MLP head
    cudaStreamWaitEvent(0, evPools, 0);
    hg_kernel<<<GG, 64>>>(gW1, gb1, gW2, gb2);
    fc_small<64><<<GG, 256>>>(p_hg, mW0, mb0, p_t0, 256, 1);
    fc_small<256><<<GG, 256>>>(p_t0, mW1, mb1, p_t1, 256, 1);
    fc_small<256><<<GG, 256>>>(p_t1, mW2, mb2, out, 256, 0);
}